// round 10
// baseline (speedup 1.0000x reference)
#include <cuda_runtime.h>
#include <cuda_fp16.h>
#include <math.h>
#include <stdint.h>
#include <stddef.h>

#define B_ 2048
#define H_ 512
#define L_ 32
#define D_ 1024
#define O_ 512

// ---------------- device scratch ----------------
__device__ float g_cx[B_ * H_];
__device__ float g_cx2[B_ * H_];
__device__ float g_gates[B_ * 2048];
__device__ float g_M2e[D_ * 2048];
__device__ float g_M2d[D_ * 2048];
__device__ float g_b0e[2048], g_b2e[2048], g_b2d[2048], g_bz[2048];
__device__ __half g_WhE1[2048 * 512], g_WhE2[2048 * 512];
__device__ __half g_WiE1[2048 * 512], g_WiE2[2048 * 512];
__device__ __half g_WhD1[2048 * 512];
__device__ __half g_WiD1[2048 * 512], g_WiD2[2048 * 512];
__device__ __half g_t2hT1[D_ * 512], g_t2hT2[D_ * 512];
__device__ __half g_h2t1[D_ * 512], g_h2t2[D_ * 512];
__device__ __half g_inW1[H_ * 512], g_inW2[H_ * 512];
__device__ __half g_outW1[O_ * 512];
__device__ __half g_x1[B_ * 512], g_x2[B_ * 512];
__device__ __half g_hxA[B_ * 512], g_hxB[B_ * 512];
__device__ __half g_hx21[B_ * 512];
__device__ int   g_imaxL[(L_ + 1) * B_];
__device__ float g_zvalL[(L_ + 1) * B_];
__device__ float g_t2hT[D_ * H_];

// ---------------- PTX helpers ----------------
__device__ __forceinline__ uint32_t smem_u32(const void* p) {
    uint32_t a;
    asm("{ .reg .u64 t; cvta.to.shared.u64 t, %1; cvt.u32.u64 %0, t; }" : "=r"(a) : "l"(p));
    return a;
}
__device__ __forceinline__ void cpa16(uint32_t sa, const void* g) {
    asm volatile("cp.async.cg.shared.global [%0], [%1], 16;" :: "r"(sa), "l"(g));
}
__device__ __forceinline__ void ldsm4(uint32_t* r, uint32_t addr) {
    asm volatile("ldmatrix.sync.aligned.m8n8.x4.shared.b16 {%0,%1,%2,%3}, [%4];"
        : "=r"(r[0]), "=r"(r[1]), "=r"(r[2]), "=r"(r[3]) : "r"(addr));
}
__device__ __forceinline__ void mma16816(float* c, const uint32_t* a, uint32_t b0, uint32_t b1) {
    asm volatile("mma.sync.aligned.m16n8k16.row.col.f32.f16.f16.f32 "
        "{%0,%1,%2,%3}, {%4,%5,%6,%7}, {%8,%9}, {%0,%1,%2,%3};"
        : "+f"(c[0]), "+f"(c[1]), "+f"(c[2]), "+f"(c[3])
        : "r"(a[0]), "r"(a[1]), "r"(a[2]), "r"(a[3]), "r"(b0), "r"(b1));
}
__device__ __forceinline__ float sigf(float x) { return 1.f / (1.f + expf(-x)); }
__device__ __forceinline__ void split2h(float v, __half* p1, __half* p2, size_t i) {
    __half h1 = __float2half_rn(v);
    p1[i] = h1; p2[i] = __float2half_rn(v - __half2float(h1));
}

#define TBA 20480u
#define TBB 10240u

// ---------------- split GEMM (3-pair for NS=2), tile 256x128 ----------------
template <int NS>
__global__ __launch_bounds__(256, 1)
void gemm_sp(const __half* a0, const __half* a1,
             const __half* b0, const __half* b1,
             const float* __restrict__ bias, float* __restrict__ C,
             int ldb, int ldC, int nck)
{
    extern __shared__ char dsm[];
    const uint32_t sb0 = smem_u32(dsm);
    const int tid = threadIdx.x, lane = tid & 31, warp = tid >> 5;
    const int wm = warp >> 1, wn = warp & 1;
    const int brow = blockIdx.y * 256, bcol = blockIdx.x * 128;
    constexpr uint32_t STB = NS * (TBA + TBB);
    const __half* As[2] = {a0, a1};
    const __half* Bs[2] = {b0, b1};

    auto load_stage = [&](int s, int kc) {
        const uint32_t st = sb0 + (uint32_t)s * STB;
        #pragma unroll
        for (int t = 0; t < NS; t++) {
            const __half* ga = As[t] + (size_t)brow * 512 + kc * 32;
            #pragma unroll
            for (int r = 0; r < 4; r++) {
                const int lin = r * 256 + tid, row = lin >> 2, c16 = lin & 3;
                cpa16(st + t * TBA + row * 80 + c16 * 16, ga + (size_t)row * 512 + c16 * 8);
            }
            const __half* gb = Bs[t] + (size_t)bcol * ldb + kc * 32;
            #pragma unroll
            for (int r = 0; r < 2; r++) {
                const int lin = r * 256 + tid, row = lin >> 2, c16 = lin & 3;
                cpa16(st + NS * TBA + t * TBB + row * 80 + c16 * 16, gb + (size_t)row * ldb + c16 * 8);
            }
        }
        asm volatile("cp.async.commit_group;" ::: "memory");
    };

    float acc[4][8][4];
    #pragma unroll
    for (int i = 0; i < 4; i++)
        #pragma unroll
        for (int j = 0; j < 8; j++)
            #pragma unroll
            for (int q = 0; q < 4; q++) acc[i][j][q] = 0.f;

    load_stage(0, 0);
    load_stage(1, 1);

    for (int c = 0; c < nck; c++) {
        const int s = c & 1;
        if (c == nck - 1) asm volatile("cp.async.wait_group 0;" ::: "memory");
        else              asm volatile("cp.async.wait_group 1;" ::: "memory");
        __syncthreads();
        const uint32_t at0 = sb0 + (uint32_t)s * STB;
        const uint32_t bt0 = at0 + NS * TBA;
        #pragma unroll
        for (int ks = 0; ks < 2; ks++) {
            uint32_t aF[NS][4][4];
            #pragma unroll
            for (int t = 0; t < NS; t++)
                #pragma unroll
                for (int i = 0; i < 4; i++) {
                    const int row = wm * 64 + i * 16 + (lane & 15);
                    ldsm4(aF[t][i], at0 + t * TBA + row * 80 + (ks * 16 + (lane >> 4) * 8) * 2);
                }
            #pragma unroll
            for (int tb = 0; tb < NS; tb++) {
                uint32_t bF[4][4];
                #pragma unroll
                for (int jp = 0; jp < 4; jp++) {
                    const int rn = wn * 64 + jp * 16 + (lane & 7) + ((lane >> 4) << 3);
                    ldsm4(bF[jp], bt0 + tb * TBB + rn * 80 + (ks * 16 + ((lane >> 3) & 1) * 8) * 2);
                }
                #pragma unroll
                for (int ta = 0; ta < NS; ta++) {
                    if (NS == 2 && ta == 1 && tb == 1) continue;   // 3-pair scheme
                    #pragma unroll
                    for (int i = 0; i < 4; i++)
                        #pragma unroll
                        for (int j = 0; j < 8; j++)
                            mma16816(acc[i][j], aF[ta][i],
                                     bF[j >> 1][(j & 1) * 2], bF[j >> 1][(j & 1) * 2 + 1]);
                }
            }
        }
        __syncthreads();
        if (c + 2 < nck) load_stage(s, c + 2);
    }

    const int er = lane >> 2, ec = (lane & 3) * 2;
    #pragma unroll
    for (int i = 0; i < 4; i++) {
        const int row = brow + wm * 64 + i * 16 + er;
        #pragma unroll
        for (int j = 0; j < 8; j++) {
            const int col = bcol + wn * 64 + j * 8 + ec;
            const float bz0 = bias[col], bz1 = bias[col + 1];
            float* c0 = C + (size_t)row * ldC + col;
            float* c1 = C + (size_t)(row + 8) * ldC + col;
            c0[0] = acc[i][j][0] + bz0; c0[1] = acc[i][j][1] + bz1;
            c1[0] = acc[i][j][2] + bz0; c1[1] = acc[i][j][3] + bz1;
        }
    }
}

// ---------------- pointwise LSTM (adds zval*M2[imax] inp contribution) ----------------
__global__ void lstm_pw_enc(const float* __restrict__ g, const float* __restrict__ M2,
                            const int* __restrict__ imax, const float* __restrict__ zval,
                            float* __restrict__ cx, __half* h1, __half* h2)
{
    const int i = blockIdx.x * 256 + threadIdx.x;
    const int b = i >> 9, h = i & 511;
    const float* gr = g + (size_t)b * 2048;
    const float* m = M2 + (size_t)imax[b] * 2048;
    const float zv = zval[b];
    const float gi = gr[h]        + zv * m[h];
    const float gf = gr[h + 512]  + zv * m[h + 512];
    const float gg = gr[h + 1024] + zv * m[h + 1024];
    const float go = gr[h + 1536] + zv * m[h + 1536];
    const float c = sigf(gf) * cx[i] + sigf(gi) * tanhf(gg);
    cx[i] = c;
    split2h(sigf(go) * tanhf(c), h1, h2, i);
}
__global__ void lstm_pw_dec(const float* __restrict__ g, const float* __restrict__ M2,
                            const int* __restrict__ imax, const float* __restrict__ zval,
                            float* __restrict__ cx, __half* h1)
{
    const int i = blockIdx.x * 256 + threadIdx.x;
    const int b = i >> 9, h = i & 511;
    const float* gr = g + (size_t)b * 2048;
    const float* m = M2 + (size_t)imax[b] * 2048;
    const float zv = zval[b];
    const float gi = gr[h]        + zv * m[h];
    const float gf = gr[h + 512]  + zv * m[h + 512];
    const float gg = gr[h + 1024] + zv * m[h + 1024];
    const float go = gr[h + 1536] + zv * m[h + 1536];
    const float c = sigf(gf) * cx[i] + sigf(gi) * tanhf(gg);
    cx[i] = c;
    h1[i] = __float2half_rn(sigf(go) * tanhf(c));
}

// ---------------- softmax + straight-through ----------------
__global__ __launch_bounds__(256)
void softmax_st(const float* __restrict__ logits, const float* __restrict__ gumbel, int t,
                float* __restrict__ onehot, float* __restrict__ messages,
                int* __restrict__ imaxO, float* __restrict__ zvalO)
{
    const int b = blockIdx.x, tid = threadIdx.x;
    const float* pre = logits + (size_t)b * (L_ * D_) + (size_t)t * D_;
    const float* gm = gumbel + ((size_t)t * B_ + b) * D_;
    float y[4]; float vmax = -INFINITY; int imax = 0;
    #pragma unroll
    for (int q = 0; q < 4; q++) {
        const int d = tid + q * 256;
        y[q] = pre[d] + gm[d];
        if (y[q] > vmax) { vmax = y[q]; imax = d; }
    }
    __shared__ float sv[256]; __shared__ int si[256]; __shared__ float ss[256];
    sv[tid] = vmax; si[tid] = imax;
    __syncthreads();
    for (int s = 128; s > 0; s >>= 1) {
        if (tid < s) {
            const float ov = sv[tid + s]; const int oi = si[tid + s];
            if (ov > sv[tid] || (ov == sv[tid] && oi < si[tid])) { sv[tid] = ov; si[tid] = oi; }
        }
        __syncthreads();
    }
    vmax = sv[0]; imax = si[0];
    float ls = 0.f;
    #pragma unroll
    for (int q = 0; q < 4; q++) ls += expf(y[q] - vmax);
    ss[tid] = ls;
    __syncthreads();
    for (int s = 128; s > 0; s >>= 1) { if (tid < s) ss[tid] += ss[tid + s]; __syncthreads(); }
    const float sm = 1.f / ss[0];
    const float zval = sm + (1.f - sm);
    float* oh = onehot + (size_t)b * (L_ * D_) + (size_t)t * D_;
    #pragma unroll
    for (int q = 0; q < 4; q++) { const int d = tid + q * 256; oh[d] = (d == imax) ? zval : 0.f; }
    if (tid == 0) {
        messages[(size_t)b * L_ + t] = (float)imax;
        imaxO[b] = imax;
        zvalO[b] = zval;
    }
}

// ---------------- prep ----------------
__global__ void split2_arr(const float* s, __half* t1, __half* t2, int n)
{ const int i = blockIdx.x * 256 + threadIdx.x; if (i < n) split2h(s[i], t1, t2, i); }
__global__ void conv1_arr(const float* s, __half* t1, int n)
{ const int i = blockIdx.x * 256 + threadIdx.x; if (i < n) t1[i] = __float2half_rn(s[i]); }
__global__ void trans_split(const float* __restrict__ W, float* __restrict__ WT,
                            __half* t1, __half* t2)
{
    const int i = blockIdx.x * 256 + threadIdx.x;
    if (i >= D_ * H_) return;
    const int d = i >> 9, h = i & 511;
    const float v = W[(size_t)h * 1024 + d];
    WT[i] = v;
    split2h(v, t1, t2, i);
}
__global__ void bias_fold(const float* __restrict__ Wih, const float* __restrict__ bih,
                          const float* __restrict__ bhh, const float* __restrict__ t2hb,
                          float* __restrict__ b0, float* __restrict__ b2)
{
    const int r = blockIdx.x * 256 + threadIdx.x;
    if (r >= 2048) return;
    const float s = bih[r] + bhh[r];
    float acc = 0.f;
    const float* wr = Wih + (size_t)r * 512;
    for (int k = 0; k < 512; k++) acc += t2hb[k] * wr[k];
    if (b0) b0[r] = s;
    b2[r] = s + acc;
}
__global__ void zero_init(__half* h1, __half* h2, __half* q1, float* c2,
                          float* bz, float* zv0, int* im0)
{
    const int i = blockIdx.x * 256 + threadIdx.x;
    if (i < B_ * 512) {
        const __half z = __float2half_rn(0.f);
        h1[i] = z; h2[i] = z; q1[i] = z; c2[i] = 0.f;
    }
    if (i < 2048) bz[i] = 0.f;
    if (i < B_) { zv0[i] = 0.f; im0[i] = 0; }
}

// ---------------- host ----------------
#define SYM(p, s) cudaGetSymbolAddress((void**)&p, s)

extern "C" void kernel_launch(void* const* d_in, const int* in_sizes, int n_in,
                              void* d_out, int out_size)
{
    const float* x = (const float*)d_in[0];
    const float* gumbel = (const float*)d_in[1];
    const float* in_W = (const float*)d_in[2];
    const float* in_b = (const float*)d_in[3];
    const float* out_W = (const float*)d_in[4];
    const float* out_b = (const float*)d_in[5];
    const float* eWih = (const float*)d_in[6];
    const float* eWhh = (const float*)d_in[7];
    const float* ebih = (const float*)d_in[8];
    const float* ebhh = (const float*)d_in[9];
    const float* dWih = (const float*)d_in[10];
    const float* dWhh = (const float*)d_in[11];
    const float* dbih = (const float*)d_in[12];
    const float* dbhh = (const float*)d_in[13];
    const float* h2t_W = (const float*)d_in[14];
    const float* h2t_b = (const float*)d_in[15];
    const float* t2h_W = (const float*)d_in[16];
    const float* t2h_b = (const float*)d_in[17];

    float* out = (float*)d_out;
    float* o_recon = out;
    float* o_oh = out + (size_t)B_ * O_;
    float* o_lg = o_oh + (size_t)B_ * L_ * D_;
    float* o_msg = o_lg + (size_t)B_ * L_ * D_;

    float *cx, *cx2, *gates, *M2e, *M2d, *b0e, *b2e, *b2d, *bz, *zvalL, *t2hT;
    int* imaxL;
    __half *WhE1, *WhE2, *WiE1, *WiE2, *WhD1, *WiD1, *WiD2;
    __half *t2hT1, *t2hT2, *h2t1, *h2t2, *inW1, *inW2, *outW1;
    __half *x1, *x2, *hxA, *hxB, *hx21;
    SYM(cx, g_cx); SYM(cx2, g_cx2); SYM(gates, g_gates);
    SYM(M2e, g_M2e); SYM(M2d, g_M2d); SYM(t2hT, g_t2hT);
    SYM(b0e, g_b0e); SYM(b2e, g_b2e); SYM(b2d, g_b2d); SYM(bz, g_bz);
    SYM(zvalL, g_zvalL); SYM(imaxL, g_imaxL);
    SYM(WhE1, g_WhE1); SYM(WhE2, g_WhE2); SYM(WiE1, g_WiE1); SYM(WiE2, g_WiE2);
    SYM(WhD1, g_WhD1); SYM(WiD1, g_WiD1); SYM(WiD2, g_WiD2);
    SYM(t2hT1, g_t2hT1); SYM(t2hT2, g_t2hT2); SYM(h2t1, g_h2t1); SYM(h2t2, g_h2t2);
    SYM(inW1, g_inW1); SYM(inW2, g_inW2); SYM(outW1, g_outW1);
    SYM(x1, g_x1); SYM(x2, g_x2);
    SYM(hxA, g_hxA); SYM(hxB, g_hxB); SYM(hx21, g_hx21);

    const int S2 = 2 * 2 * (TBA + TBB);   // 122880
    const int S1 = 2 * 1 * (TBA + TBB);   // 61440
    cudaFuncSetAttribute(gemm_sp<2>, cudaFuncAttributeMaxDynamicSharedMemorySize, S2);
    cudaFuncSetAttribute(gemm_sp<1>, cudaFuncAttributeMaxDynamicSharedMemorySize, S1);

    // ---- prep ----
    split2_arr<<<4096, 256>>>(eWhh, WhE1, WhE2, 2048 * 512);
    split2_arr<<<4096, 256>>>(eWih, WiE1, WiE2, 2048 * 512);
    conv1_arr<<<4096, 256>>>(dWhh, WhD1, 2048 * 512);
    split2_arr<<<4096, 256>>>(dWih, WiD1, WiD2, 2048 * 512);
    trans_split<<<2048, 256>>>(t2h_W, t2hT, t2hT1, t2hT2);
    split2_arr<<<2048, 256>>>(h2t_W, h2t1, h2t2, D_ * 512);   // FIXED: was <<<1024>>> (half-filled!)
    split2_arr<<<1024, 256>>>(in_W, inW1, inW2, H_ * 512);
    conv1_arr<<<1024, 256>>>(out_W, outW1, O_ * 512);
    split2_arr<<<4096, 256>>>(x, x1, x2, B_ * 512);
    bias_fold<<<8, 256>>>(eWih, ebih, ebhh, t2h_b, b0e, b2e);
    bias_fold<<<8, 256>>>(dWih, dbih, dbhh, t2h_b, nullptr, b2d);
    zero_init<<<4096, 256>>>(hxA, hxB, hx21, cx2, bz, zvalL, imaxL);

    // M2e = t2hT @ eWih^T, M2d = t2hT @ dWih^T  (fp32-grade 3-pair)
    gemm_sp<2><<<dim3(16, 4), 256, S2>>>(t2hT1, t2hT2, WiE1, WiE2, bz, M2e, 512, 2048, 16);
    gemm_sp<2><<<dim3(16, 4), 256, S2>>>(t2hT1, t2hT2, WiD1, WiD2, bz, M2d, 512, 2048, 16);

    // cx = x @ in_W^T + in_b
    gemm_sp<2><<<dim3(4, 8), 256, S2>>>(x1, x2, inW1, inW2, in_b, cx, 512, 512, 16);

    // ---- encoder (gate GEMM K=512 over hx; inp via M2e gather in pointwise) ----
    for (int t = 0; t < L_; t++) {
        gemm_sp<2><<<dim3(16, 8), 256, S2>>>(hxA, hxB, WhE1, WhE2,
            (t == 0) ? b0e : b2e, gates, 512, 2048, 16);
        lstm_pw_enc<<<4096, 256>>>(gates, M2e, imaxL + (size_t)t * B_,
            zvalL + (size_t)t * B_, cx, hxA, hxB);
        gemm_sp<2><<<dim3(8, 8), 256, S2>>>(hxA, hxB, h2t1, h2t2, h2t_b,
            o_lg + (size_t)t * D_, 512, L_ * D_, 16);
        softmax_st<<<B_, 256>>>(o_lg, gumbel, t, o_oh, o_msg,
            imaxL + (size_t)(t + 1) * B_, zvalL + (size_t)(t + 1) * B_);
    }

    // ---- decoder (K=512 over hx; z via M2d gather in pointwise) ----
    for (int t = 0; t < L_; t++) {
        gemm_sp<1><<<dim3(16, 8), 256, S1>>>(hx21, hx21, WhD1, WhD1, b2d,
            gates, 512, 2048, 16);
        lstm_pw_dec<<<4096, 256>>>(gates, M2d, imaxL + (size_t)(t + 1) * B_,
            zvalL + (size_t)(t + 1) * B_, cx2, hx21);
    }
    gemm_sp<1><<<dim3(4, 8), 256, S1>>>(hx21, hx21, outW1, outW1, out_b, o_recon,
                                        512, 512, 16);
}

// round 11
// speedup vs baseline: 1.2805x; 1.2805x over previous
#include <cuda_runtime.h>
#include <cuda_fp16.h>
#include <math.h>
#include <stdint.h>
#include <stddef.h>

#define B_ 2048
#define H_ 512
#define L_ 32
#define D_ 1024
#define O_ 512

// ---------------- device scratch ----------------
__device__ float g_cx[B_ * H_];
__device__ float g_cx2[B_ * H_];
__device__ float g_M2e[D_ * 2048];   // interleaved cols
__device__ float g_M2d[D_ * 2048];   // interleaved cols
__device__ float g_b0e[2048], g_b2e[2048], g_b2d[2048], g_bz[2048];
__device__ __half g_WhE1[2048 * 512], g_WhE2[2048 * 512];   // interleaved rows
__device__ __half g_WiE1[2048 * 512], g_WiE2[2048 * 512];   // interleaved rows
__device__ __half g_WhD1[2048 * 512];                        // interleaved rows
__device__ __half g_WiD1[2048 * 512], g_WiD2[2048 * 512];   // interleaved rows
__device__ __half g_t2hT1[D_ * 512], g_t2hT2[D_ * 512];
__device__ __half g_h2t1[D_ * 512], g_h2t2[D_ * 512];
__device__ __half g_inW1[H_ * 512], g_inW2[H_ * 512];
__device__ __half g_outW1[O_ * 512];
__device__ __half g_x1[B_ * 512], g_x2[B_ * 512];
__device__ __half g_hxA[B_ * 512], g_hxB[B_ * 512];
__device__ __half g_hxC[B_ * 512], g_hxD[B_ * 512];
__device__ __half g_hx21[B_ * 512], g_hx21b[B_ * 512];
__device__ int   g_imaxL[(L_ + 1) * B_];
__device__ float g_zvalL[(L_ + 1) * B_];

// ---------------- PTX helpers ----------------
__device__ __forceinline__ uint32_t smem_u32(const void* p) {
    uint32_t a;
    asm("{ .reg .u64 t; cvta.to.shared.u64 t, %1; cvt.u32.u64 %0, t; }" : "=r"(a) : "l"(p));
    return a;
}
__device__ __forceinline__ void cpa16(uint32_t sa, const void* g) {
    asm volatile("cp.async.cg.shared.global [%0], [%1], 16;" :: "r"(sa), "l"(g));
}
__device__ __forceinline__ void ldsm4(uint32_t* r, uint32_t addr) {
    asm volatile("ldmatrix.sync.aligned.m8n8.x4.shared.b16 {%0,%1,%2,%3}, [%4];"
        : "=r"(r[0]), "=r"(r[1]), "=r"(r[2]), "=r"(r[3]) : "r"(addr));
}
__device__ __forceinline__ void mma16816(float* c, const uint32_t* a, uint32_t b0, uint32_t b1) {
    asm volatile("mma.sync.aligned.m16n8k16.row.col.f32.f16.f16.f32 "
        "{%0,%1,%2,%3}, {%4,%5,%6,%7}, {%8,%9}, {%0,%1,%2,%3};"
        : "+f"(c[0]), "+f"(c[1]), "+f"(c[2]), "+f"(c[3])
        : "r"(a[0]), "r"(a[1]), "r"(a[2]), "r"(a[3]), "r"(b0), "r"(b1));
}
__device__ __forceinline__ float sigf(float x) { return 1.f / (1.f + expf(-x)); }
__device__ __forceinline__ void split2h(float v, __half* p1, __half* p2, size_t i) {
    __half h1 = __float2half_rn(v);
    p1[i] = h1; p2[i] = __float2half_rn(v - __half2float(h1));
}

#define TBA 20480u
#define TBB 10240u

// ---------------- split GEMM (3-pair for NS=2), tile 256x128 — proven core ----------------
template <int NS>
__global__ __launch_bounds__(256, 1)
void gemm_sp(const __half* a0, const __half* a1,
             const __half* b0, const __half* b1,
             const float* __restrict__ bias, float* __restrict__ C,
             int ldb, int ldC, int nck)
{
    extern __shared__ char dsm[];
    const uint32_t sb0 = smem_u32(dsm);
    const int tid = threadIdx.x, lane = tid & 31, warp = tid >> 5;
    const int wm = warp >> 1, wn = warp & 1;
    const int brow = blockIdx.y * 256, bcol = blockIdx.x * 128;
    constexpr uint32_t STB = NS * (TBA + TBB);
    const __half* As[2] = {a0, a1};
    const __half* Bs[2] = {b0, b1};

    auto load_stage = [&](int s, int kc) {
        const uint32_t st = sb0 + (uint32_t)s * STB;
        #pragma unroll
        for (int t = 0; t < NS; t++) {
            const __half* ga = As[t] + (size_t)brow * 512 + kc * 32;
            #pragma unroll
            for (int r = 0; r < 4; r++) {
                const int lin = r * 256 + tid, row = lin >> 2, c16 = lin & 3;
                cpa16(st + t * TBA + row * 80 + c16 * 16, ga + (size_t)row * 512 + c16 * 8);
            }
            const __half* gb = Bs[t] + (size_t)bcol * ldb + kc * 32;
            #pragma unroll
            for (int r = 0; r < 2; r++) {
                const int lin = r * 256 + tid, row = lin >> 2, c16 = lin & 3;
                cpa16(st + NS * TBA + t * TBB + row * 80 + c16 * 16, gb + (size_t)row * ldb + c16 * 8);
            }
        }
        asm volatile("cp.async.commit_group;" ::: "memory");
    };

    float acc[4][8][4];
    #pragma unroll
    for (int i = 0; i < 4; i++)
        #pragma unroll
        for (int j = 0; j < 8; j++)
            #pragma unroll
            for (int q = 0; q < 4; q++) acc[i][j][q] = 0.f;

    load_stage(0, 0);
    load_stage(1, 1);

    for (int c = 0; c < nck; c++) {
        const int s = c & 1;
        if (c == nck - 1) asm volatile("cp.async.wait_group 0;" ::: "memory");
        else              asm volatile("cp.async.wait_group 1;" ::: "memory");
        __syncthreads();
        const uint32_t at0 = sb0 + (uint32_t)s * STB;
        const uint32_t bt0 = at0 + NS * TBA;
        #pragma unroll
        for (int ks = 0; ks < 2; ks++) {
            uint32_t aF[NS][4][4];
            #pragma unroll
            for (int t = 0; t < NS; t++)
                #pragma unroll
                for (int i = 0; i < 4; i++) {
                    const int row = wm * 64 + i * 16 + (lane & 15);
                    ldsm4(aF[t][i], at0 + t * TBA + row * 80 + (ks * 16 + (lane >> 4) * 8) * 2);
                }
            #pragma unroll
            for (int tb = 0; tb < NS; tb++) {
                uint32_t bF[4][4];
                #pragma unroll
                for (int jp = 0; jp < 4; jp++) {
                    const int rn = wn * 64 + jp * 16 + (lane & 7) + ((lane >> 4) << 3);
                    ldsm4(bF[jp], bt0 + tb * TBB + rn * 80 + (ks * 16 + ((lane >> 3) & 1) * 8) * 2);
                }
                #pragma unroll
                for (int ta = 0; ta < NS; ta++) {
                    if (NS == 2 && ta == 1 && tb == 1) continue;
                    #pragma unroll
                    for (int i = 0; i < 4; i++)
                        #pragma unroll
                        for (int j = 0; j < 8; j++)
                            mma16816(acc[i][j], aF[ta][i],
                                     bF[j >> 1][(j & 1) * 2], bF[j >> 1][(j & 1) * 2 + 1]);
                }
            }
        }
        __syncthreads();
        if (c + 2 < nck) load_stage(s, c + 2);
    }

    const int er = lane >> 2, ec = (lane & 3) * 2;
    #pragma unroll
    for (int i = 0; i < 4; i++) {
        const int row = brow + wm * 64 + i * 16 + er;
        #pragma unroll
        for (int j = 0; j < 8; j++) {
            const int col = bcol + wn * 64 + j * 8 + ec;
            const float bz0 = bias[col], bz1 = bias[col + 1];
            float* c0 = C + (size_t)row * ldC + col;
            float* c1 = C + (size_t)(row + 8) * ldC + col;
            c0[0] = acc[i][j][0] + bz0; c0[1] = acc[i][j][1] + bz1;
            c1[0] = acc[i][j][2] + bz0; c1[1] = acc[i][j][3] + bz1;
        }
    }
}

// ===== fused gate GEMM + LSTM cell. K=512 (hx); interleaved cols n=4h+g; M2I gather =====
template <int NS>
__global__ __launch_bounds__(256, 1)
void gemm_gate(const __half* a0, const __half* a1,
               const __half* b0, const __half* b1,
               const float* __restrict__ biasI, const float* __restrict__ M2I,
               const int* __restrict__ imax, const float* __restrict__ zval,
               float* __restrict__ cx, __half* wo1, __half* wo2)
{
    extern __shared__ char dsm[];
    const uint32_t sb0 = smem_u32(dsm);
    const int tid = threadIdx.x, lane = tid & 31, warp = tid >> 5;
    const int wm = warp >> 1, wn = warp & 1;
    const int brow = blockIdx.y * 256, bcol = blockIdx.x * 128;
    constexpr uint32_t STB = NS * (TBA + TBB);
    const __half* As[2] = {a0, a1};
    const __half* Bs[2] = {b0, b1};
    const int nck = 16;

    auto load_stage = [&](int s, int kc) {
        const uint32_t st = sb0 + (uint32_t)s * STB;
        #pragma unroll
        for (int t = 0; t < NS; t++) {
            const __half* ga = As[t] + (size_t)brow * 512 + kc * 32;
            #pragma unroll
            for (int r = 0; r < 4; r++) {
                const int lin = r * 256 + tid, row = lin >> 2, c16 = lin & 3;
                cpa16(st + t * TBA + row * 80 + c16 * 16, ga + (size_t)row * 512 + c16 * 8);
            }
            const __half* gb = Bs[t] + (size_t)bcol * 512 + kc * 32;
            #pragma unroll
            for (int r = 0; r < 2; r++) {
                const int lin = r * 256 + tid, row = lin >> 2, c16 = lin & 3;
                cpa16(st + NS * TBA + t * TBB + row * 80 + c16 * 16, gb + (size_t)row * 512 + c16 * 8);
            }
        }
        asm volatile("cp.async.commit_group;" ::: "memory");
    };

    float acc[4][8][4];
    #pragma unroll
    for (int i = 0; i < 4; i++)
        #pragma unroll
        for (int j = 0; j < 8; j++)
            #pragma unroll
            for (int q = 0; q < 4; q++) acc[i][j][q] = 0.f;

    load_stage(0, 0);
    load_stage(1, 1);

    for (int c = 0; c < nck; c++) {
        const int s = c & 1;
        if (c == nck - 1) asm volatile("cp.async.wait_group 0;" ::: "memory");
        else              asm volatile("cp.async.wait_group 1;" ::: "memory");
        __syncthreads();
        const uint32_t at0 = sb0 + (uint32_t)s * STB;
        const uint32_t bt0 = at0 + NS * TBA;
        #pragma unroll
        for (int ks = 0; ks < 2; ks++) {
            uint32_t aF[NS][4][4];
            #pragma unroll
            for (int t = 0; t < NS; t++)
                #pragma unroll
                for (int i = 0; i < 4; i++) {
                    const int row = wm * 64 + i * 16 + (lane & 15);
                    ldsm4(aF[t][i], at0 + t * TBA + row * 80 + (ks * 16 + (lane >> 4) * 8) * 2);
                }
            #pragma unroll
            for (int tb = 0; tb < NS; tb++) {
                uint32_t bF[4][4];
                #pragma unroll
                for (int jp = 0; jp < 4; jp++) {
                    const int rn = wn * 64 + jp * 16 + (lane & 7) + ((lane >> 4) << 3);
                    ldsm4(bF[jp], bt0 + tb * TBB + rn * 80 + (ks * 16 + ((lane >> 3) & 1) * 8) * 2);
                }
                #pragma unroll
                for (int ta = 0; ta < NS; ta++) {
                    if (NS == 2 && ta == 1 && tb == 1) continue;
                    #pragma unroll
                    for (int i = 0; i < 4; i++)
                        #pragma unroll
                        for (int j = 0; j < 8; j++)
                            mma16816(acc[i][j], aF[ta][i],
                                     bF[j >> 1][(j & 1) * 2], bF[j >> 1][(j & 1) * 2 + 1]);
                }
            }
        }
        __syncthreads();
        if (c + 2 < nck) load_stage(s, c + 2);
    }

    // fused LSTM epilogue: cols n=4h+g; lane pair (lane^1) exchanges (i,f)<->(g,o)
    const int er = lane >> 2, ec = (lane & 3) * 2;
    #pragma unroll
    for (int i = 0; i < 4; i++) {
        const int r0 = brow + wm * 64 + i * 16 + er;
        const int r1 = r0 + 8;
        const float zv0 = zval[r0], zv1 = zval[r1];
        const float* m0 = M2I + (size_t)imax[r0] * 2048;
        const float* m1 = M2I + (size_t)imax[r1] * 2048;
        #pragma unroll
        for (int j = 0; j < 8; j++) {
            const int col = bcol + wn * 64 + j * 8 + ec;
            const float bz0 = biasI[col], bz1 = biasI[col + 1];
            const float v0 = acc[i][j][0] + bz0 + zv0 * m0[col];
            const float v1 = acc[i][j][1] + bz1 + zv0 * m0[col + 1];
            const float v2 = acc[i][j][2] + bz0 + zv1 * m1[col];
            const float v3 = acc[i][j][3] + bz1 + zv1 * m1[col + 1];
            const float p0 = __shfl_xor_sync(0xffffffffu, v0, 1);
            const float p1 = __shfl_xor_sync(0xffffffffu, v1, 1);
            const float p2 = __shfl_xor_sync(0xffffffffu, v2, 1);
            const float p3 = __shfl_xor_sync(0xffffffffu, v3, 1);
            const int h = col >> 2;
            int rw; float gi, gf, gg, go;
            if ((lane & 1) == 0) { rw = r0; gi = v0; gf = v1; gg = p0; go = p1; }
            else                 { rw = r1; gi = p2; gf = p3; gg = v2; go = v3; }
            const size_t idx = (size_t)rw * 512 + h;
            const float cnew = sigf(gf) * cx[idx] + sigf(gi) * tanhf(gg);
            cx[idx] = cnew;
            const float hv = sigf(go) * tanhf(cnew);
            if (NS == 2) split2h(hv, wo1, wo2, idx);
            else         wo1[idx] = __float2half_rn(hv);
        }
    }
}

// ---------------- softmax + straight-through (R10-proven) ----------------
__global__ __launch_bounds__(256)
void softmax_st(const float* __restrict__ logits, const float* __restrict__ gumbel, int t,
                float* __restrict__ onehot, float* __restrict__ messages,
                int* __restrict__ imaxO, float* __restrict__ zvalO)
{
    const int b = blockIdx.x, tid = threadIdx.x;
    const float* pre = logits + (size_t)b * (L_ * D_) + (size_t)t * D_;
    const float* gm = gumbel + ((size_t)t * B_ + b) * D_;
    float y[4]; float vmax = -INFINITY; int imax = 0;
    #pragma unroll
    for (int q = 0; q < 4; q++) {
        const int d = tid + q * 256;
        y[q] = pre[d] + gm[d];
        if (y[q] > vmax) { vmax = y[q]; imax = d; }
    }
    __shared__ float sv[256]; __shared__ int si[256]; __shared__ float ss[256];
    sv[tid] = vmax; si[tid] = imax;
    __syncthreads();
    for (int s = 128; s > 0; s >>= 1) {
        if (tid < s) {
            const float ov = sv[tid + s]; const int oi = si[tid + s];
            if (ov > sv[tid] || (ov == sv[tid] && oi < si[tid])) { sv[tid] = ov; si[tid] = oi; }
        }
        __syncthreads();
    }
    vmax = sv[0]; imax = si[0];
    float ls = 0.f;
    #pragma unroll
    for (int q = 0; q < 4; q++) ls += expf(y[q] - vmax);
    ss[tid] = ls;
    __syncthreads();
    for (int s = 128; s > 0; s >>= 1) { if (tid < s) ss[tid] += ss[tid + s]; __syncthreads(); }
    const float sm = 1.f / ss[0];
    const float zval = sm + (1.f - sm);
    float* oh = onehot + (size_t)b * (L_ * D_) + (size_t)t * D_;
    #pragma unroll
    for (int q = 0; q < 4; q++) { const int d = tid + q * 256; oh[d] = (d == imax) ? zval : 0.f; }
    if (tid == 0) {
        messages[(size_t)b * L_ + t] = (float)imax;
        imaxO[b] = imax;
        zvalO[b] = zval;
    }
}

// ---------------- consolidated prep (single kernel, segmented) ----------------
__global__ void prep_all(const float* __restrict__ eWih, const float* __restrict__ eWhh,
                         const float* __restrict__ dWih, const float* __restrict__ dWhh,
                         const float* __restrict__ t2h_W, const float* __restrict__ h2t_W,
                         const float* __restrict__ in_W, const float* __restrict__ out_W,
                         const float* __restrict__ x,
                         __half* WhE1, __half* WhE2, __half* WiE1, __half* WiE2,
                         __half* WhD1, __half* WiD1, __half* WiD2,
                         __half* t2hT1, __half* t2hT2, __half* h2t1, __half* h2t2,
                         __half* inW1, __half* inW2, __half* outW1,
                         __half* x1, __half* x2,
                         __half* hxA, __half* hxB, __half* hx21,
                         float* cx2, float* bz, float* zv0, int* im0)
{
    int i = blockIdx.x * 256 + threadIdx.x;
    // seg 0: enc Whh interleaved split  [1048576]
    if (i < 1048576) {
        const int n = i >> 9, k = i & 511, r = ((n & 3) << 9) + (n >> 2);
        split2h(eWhh[(size_t)r * 512 + k], WhE1, WhE2, i);
        return;
    }
    i -= 1048576;
    // seg 1: enc Wih interleaved split  [1048576]
    if (i < 1048576) {
        const int n = i >> 9, k = i & 511, r = ((n & 3) << 9) + (n >> 2);
        split2h(eWih[(size_t)r * 512 + k], WiE1, WiE2, i);
        return;
    }
    i -= 1048576;
    // seg 2: dec Whh interleaved conv  [1048576]
    if (i < 1048576) {
        const int n = i >> 9, k = i & 511, r = ((n & 3) << 9) + (n >> 2);
        WhD1[i] = __float2half_rn(dWhh[(size_t)r * 512 + k]);
        return;
    }
    i -= 1048576;
    // seg 3: dec Wih interleaved split  [1048576]
    if (i < 1048576) {
        const int n = i >> 9, k = i & 511, r = ((n & 3) << 9) + (n >> 2);
        split2h(dWih[(size_t)r * 512 + k], WiD1, WiD2, i);
        return;
    }
    i -= 1048576;
    // seg 4: t2h transpose + split  [524288]
    if (i < 524288) {
        const int d = i >> 9, h = i & 511;
        split2h(t2h_W[(size_t)h * 1024 + d], t2hT1, t2hT2, i);
        return;
    }
    i -= 524288;
    // seg 5: h2t split  [524288]
    if (i < 524288) { split2h(h2t_W[i], h2t1, h2t2, i); return; }
    i -= 524288;
    // seg 6: in_W split  [262144]
    if (i < 262144) { split2h(in_W[i], inW1, inW2, i); return; }
    i -= 262144;
    // seg 7: out_W conv  [262144]
    if (i < 262144) { outW1[i] = __float2half_rn(out_W[i]); return; }
    i -= 262144;
    // seg 8: x split  [1048576]
    if (i < 1048576) { split2h(x[i], x1, x2, i); return; }
    i -= 1048576;
    // seg 9: zero init  [1048576]
    if (i < 1048576) {
        const __half z = __float2half_rn(0.f);
        hxA[i] = z; hxB[i] = z; hx21[i] = z; cx2[i] = 0.f;
        if (i < 2048) { bz[i] = 0.f; }
        if (i < B_) { zv0[i] = 0.f; im0[i] = 0; }
    }
}
// total elements: 4*1048576 + 2*524288 + 2*262144 + 2*1048576 = 7864320 -> 30720 blocks

__global__ void bias_fold2(const float* __restrict__ eWih, const float* __restrict__ ebih,
                           const float* __restrict__ ebhh,
                           const float* __restrict__ dWih, const float* __restrict__ dbih,
                           const float* __restrict__ dbhh,
                           const float* __restrict__ t2hb,
                           float* __restrict__ b0e, float* __restrict__ b2e,
                           float* __restrict__ b2d)
{
    const int tid = blockIdx.x * 256 + threadIdx.x;
    if (tid < 2048) {
        const int n = tid, r = ((n & 3) << 9) + (n >> 2);
        const float s = ebih[r] + ebhh[r];
        float acc = 0.f;
        const float* wr = eWih + (size_t)r * 512;
        for (int k = 0; k < 512; k++) acc += t2hb[k] * wr[k];
        b0e[n] = s; b2e[n] = s + acc;
    } else if (tid < 4096) {
        const int n = tid - 2048, r = ((n & 3) << 9) + (n >> 2);
        const float s = dbih[r] + dbhh[r];
        float acc = 0.f;
        const float* wr = dWih + (size_t)r * 512;
        for (int k = 0; k < 512; k++) acc += t2hb[k] * wr[k];
        b2d[n] = s + acc;
    }
}

// ---------------- host ----------------
#define SYM(p, s) cudaGetSymbolAddress((void**)&p, s)

extern "C" void kernel_launch(void* const* d_in, const int* in_sizes, int n_in,
                              void* d_out, int out_size)
{
    const float* x = (const float*)d_in[0];
    const float* gumbel = (const float*)d_in[1];
    const float* in_W = (const float*)d_in[2];
    const float* in_b = (const float*)d_in[3];
    const float* out_W = (const float*)d_in[4];
    const float* out_b = (const float*)d_in[5];
    const float* eWih = (const float*)d_in[6];
    const float* eWhh = (const float*)d_in[7];
    const float* ebih = (const float*)d_in[8];
    const float* ebhh = (const float*)d_in[9];
    const float* dWih = (const float*)d_in[10];
    const float* dWhh = (const float*)d_in[11];
    const float* dbih = (const float*)d_in[12];
    const float* dbhh = (const float*)d_in[13];
    const float* h2t_W = (const float*)d_in[14];
    const float* h2t_b = (const float*)d_in[15];
    const float* t2h_W = (const float*)d_in[16];
    const float* t2h_b = (const float*)d_in[17];

    float* out = (float*)d_out;
    float* o_recon = out;
    float* o_oh = out + (size_t)B_ * O_;
    float* o_lg = o_oh + (size_t)B_ * L_ * D_;
    float* o_msg = o_lg + (size_t)B_ * L_ * D_;

    float *cx, *cx2, *M2e, *M2d, *b0e, *b2e, *b2d, *bz, *zvalL;
    int* imaxL;
    __half *WhE1, *WhE2, *WiE1, *WiE2, *WhD1, *WiD1, *WiD2;
    __half *t2hT1, *t2hT2, *h2t1, *h2t2, *inW1, *inW2, *outW1;
    __half *x1, *x2, *hxA, *hxB, *hxC, *hxD, *hx21, *hx21b;
    SYM(cx, g_cx); SYM(cx2, g_cx2);
    SYM(M2e, g_M2e); SYM(M2d, g_M2d);
    SYM(b0e, g_b0e); SYM(b2e, g_b2e); SYM(b2d, g_b2d); SYM(bz, g_bz);
    SYM(zvalL, g_zvalL); SYM(imaxL, g_imaxL);
    SYM(WhE1, g_WhE1); SYM(WhE2, g_WhE2); SYM(WiE1, g_WiE1); SYM(WiE2, g_WiE2);
    SYM(WhD1, g_WhD1); SYM(WiD1, g_WiD1); SYM(WiD2, g_WiD2);
    SYM(t2hT1, g_t2hT1); SYM(t2hT2, g_t2hT2); SYM(h2t1, g_h2t1); SYM(h2t2, g_h2t2);
    SYM(inW1, g_inW1); SYM(inW2, g_inW2); SYM(outW1, g_outW1);
    SYM(x1, g_x1); SYM(x2, g_x2);
    SYM(hxA, g_hxA); SYM(hxB, g_hxB); SYM(hxC, g_hxC); SYM(hxD, g_hxD);
    SYM(hx21, g_hx21); SYM(hx21b, g_hx21b);

    const int S2 = 2 * 2 * (TBA + TBB);   // 122880
    const int S1 = 2 * 1 * (TBA + TBB);   // 61440
    cudaFuncSetAttribute(gemm_sp<2>, cudaFuncAttributeMaxDynamicSharedMemorySize, S2);
    cudaFuncSetAttribute(gemm_sp<1>, cudaFuncAttributeMaxDynamicSharedMemorySize, S1);
    cudaFuncSetAttribute(gemm_gate<2>, cudaFuncAttributeMaxDynamicSharedMemorySize, S2);
    cudaFuncSetAttribute(gemm_gate<1>, cudaFuncAttributeMaxDynamicSharedMemorySize, S1);

    // launch 0: all elementwise prep
    prep_all<<<30720, 256>>>(eWih, eWhh, dWih, dWhh, t2h_W, h2t_W, in_W, out_W, x,
                             WhE1, WhE2, WiE1, WiE2, WhD1, WiD1, WiD2,
                             t2hT1, t2hT2, h2t1, h2t2, inW1, inW2, outW1,
                             x1, x2, hxA, hxB, hx21, cx2, bz, zvalL, imaxL);
    // launch 1: bias folds
    bias_fold2<<<16, 256>>>(eWih, ebih, ebhh, dWih, dbih, dbhh, t2h_b, b0e, b2e, b2d);
    // launch 2-3: M2eI / M2dI (interleaved cols)
    gemm_sp<2><<<dim3(16, 4), 256, S2>>>(t2hT1, t2hT2, WiE1, WiE2, bz, M2e, 512, 2048, 16);
    gemm_sp<2><<<dim3(16, 4), 256, S2>>>(t2hT1, t2hT2, WiD1, WiD2, bz, M2d, 512, 2048, 16);
    // launch 4: cx = x @ in_W^T + in_b
    gemm_sp<2><<<dim3(4, 8), 256, S2>>>(x1, x2, inW1, inW2, in_b, cx, 512, 512, 16);

    // ---- encoder: fused gate+LSTM (launch 5 = first gate -> ncu target) ----
    for (int t = 0; t < L_; t++) {
        __half *hr1 = (t & 1) ? hxC : hxA, *hr2 = (t & 1) ? hxD : hxB;
        __half *hw1 = (t & 1) ? hxA : hxC, *hw2 = (t & 1) ? hxB : hxD;
        gemm_gate<2><<<dim3(16, 8), 256, S2>>>(hr1, hr2, WhE1, WhE2,
            (t == 0) ? b0e : b2e, M2e, imaxL + (size_t)t * B_, zvalL + (size_t)t * B_,
            cx, hw1, hw2);
        gemm_sp<2><<<dim3(8, 8), 256, S2>>>(hw1, hw2, h2t1, h2t2, h2t_b,
            o_lg + (size_t)t * D_, 512, L_ * D_, 16);
        softmax_st<<<B_, 256>>>(o_lg, gumbel, t, o_oh, o_msg,
            imaxL + (size_t)(t + 1) * B_, zvalL + (size_t)(t + 1) * B_);
    }

    // ---- decoder: 1 fused kernel per step ----
    for (int t = 0; t < L_; t++) {
        __half* hr = (t & 1) ? hx21b : hx21;
        __half* hw = (t & 1) ? hx21 : hx21b;
        gemm_gate<1><<<dim3(16, 8), 256, S1>>>(hr, hr, WhD1, WhD1, b2d, M2d,
            imaxL + (size_t)(t + 1) * B_, zvalL + (size_t)(t + 1) * B_,
            cx2, hw, nullptr);
    }
    // L=32 even: t=31 odd wrote hx21
    gemm_sp<1><<<dim3(4, 8), 256, S1>>>(hx21, hx21, outW1, outW1, out_b, o_recon,
                                        512, 512, 16);
}

// round 12
// speedup vs baseline: 1.4071x; 1.0989x over previous
#include <cuda_runtime.h>
#include <cuda_fp16.h>
#include <math.h>
#include <stdint.h>
#include <stddef.h>

#define B_ 2048
#define H_ 512
#define L_ 32
#define D_ 1024
#define O_ 512

// ---------------- device scratch ----------------
__device__ float g_cx[B_ * H_];
__device__ float g_cx2[B_ * H_];
__device__ float g_M2e[D_ * 2048];   // interleaved cols
__device__ float g_M2d[D_ * 2048];   // interleaved cols
__device__ float g_b0e[2048], g_b2e[2048], g_b2d[2048], g_bz[2048];
__device__ __half g_WhE1[2048 * 512], g_WhE2[2048 * 512];   // interleaved rows
__device__ __half g_WiE1[2048 * 512], g_WiE2[2048 * 512];   // interleaved rows
__device__ __half g_WhD1[2048 * 512];                        // interleaved rows
__device__ __half g_WiD1[2048 * 512], g_WiD2[2048 * 512];   // interleaved rows
__device__ __half g_t2hT1[D_ * 512], g_t2hT2[D_ * 512];
__device__ __half g_h2t1[D_ * 512], g_h2t2[D_ * 512];
__device__ __half g_inW1[H_ * 512], g_inW2[H_ * 512];
__device__ __half g_outW1[O_ * 512];
__device__ __half g_x1[B_ * 512], g_x2[B_ * 512];
__device__ __half g_hxA[B_ * 512], g_hxB[B_ * 512];
__device__ __half g_hxC[B_ * 512], g_hxD[B_ * 512];
__device__ __half g_hx21[B_ * 512], g_hx21b[B_ * 512];
__device__ int   g_imaxL[(L_ + 1) * B_];
__device__ float g_zvalL[(L_ + 1) * B_];

// ---------------- PTX helpers ----------------
__device__ __forceinline__ uint32_t smem_u32(const void* p) {
    uint32_t a;
    asm("{ .reg .u64 t; cvta.to.shared.u64 t, %1; cvt.u32.u64 %0, t; }" : "=r"(a) : "l"(p));
    return a;
}
__device__ __forceinline__ void cpa16(uint32_t sa, const void* g) {
    asm volatile("cp.async.cg.shared.global [%0], [%1], 16;" :: "r"(sa), "l"(g));
}
__device__ __forceinline__ void ldsm4(uint32_t* r, uint32_t addr) {
    asm volatile("ldmatrix.sync.aligned.m8n8.x4.shared.b16 {%0,%1,%2,%3}, [%4];"
        : "=r"(r[0]), "=r"(r[1]), "=r"(r[2]), "=r"(r[3]) : "r"(addr));
}
__device__ __forceinline__ void mma16816(float* c, const uint32_t* a, uint32_t b0, uint32_t b1) {
    asm volatile("mma.sync.aligned.m16n8k16.row.col.f32.f16.f16.f32 "
        "{%0,%1,%2,%3}, {%4,%5,%6,%7}, {%8,%9}, {%0,%1,%2,%3};"
        : "+f"(c[0]), "+f"(c[1]), "+f"(c[2]), "+f"(c[3])
        : "r"(a[0]), "r"(a[1]), "r"(a[2]), "r"(a[3]), "r"(b0), "r"(b1));
}
__device__ __forceinline__ float sigf(float x) { return 1.f / (1.f + expf(-x)); }
__device__ __forceinline__ void split2h(float v, __half* p1, __half* p2, size_t i) {
    __half h1 = __float2half_rn(v);
    p1[i] = h1; p2[i] = __float2half_rn(v - __half2float(h1));
}

#define TBA 20480u    // 256 rows x 80 B
#define TBB 10240u    // 128 rows x 80 B

// ======== 256x128-tile split GEMM, 3-stage pipeline, ONE sync/chunk ========
template <int NS>
__global__ __launch_bounds__(256, 1)
void gemm_sp(const __half* a0, const __half* a1,
             const __half* b0, const __half* b1,
             const float* __restrict__ bias, float* __restrict__ C,
             int ldb, int ldC, int nck)
{
    extern __shared__ char dsm[];
    const uint32_t sb0 = smem_u32(dsm);
    const int tid = threadIdx.x, lane = tid & 31, warp = tid >> 5;
    const int wm = warp >> 1, wn = warp & 1;
    const int brow = blockIdx.y * 256, bcol = blockIdx.x * 128;
    constexpr uint32_t STB = NS * (TBA + TBB);
    const __half* As[2] = {a0, a1};
    const __half* Bs[2] = {b0, b1};

    auto load_stage = [&](int slot, int kc) {
        const uint32_t st = sb0 + (uint32_t)slot * STB;
        #pragma unroll
        for (int t = 0; t < NS; t++) {
            const __half* ga = As[t] + (size_t)brow * 512 + kc * 32;
            #pragma unroll
            for (int r = 0; r < 4; r++) {
                const int lin = r * 256 + tid, row = lin >> 2, c16 = lin & 3;
                cpa16(st + t * TBA + row * 80 + c16 * 16, ga + (size_t)row * 512 + c16 * 8);
            }
            const __half* gb = Bs[t] + (size_t)bcol * ldb + kc * 32;
            #pragma unroll
            for (int r = 0; r < 2; r++) {
                const int lin = r * 256 + tid, row = lin >> 2, c16 = lin & 3;
                cpa16(st + NS * TBA + t * TBB + row * 80 + c16 * 16, gb + (size_t)row * ldb + c16 * 8);
            }
        }
        asm volatile("cp.async.commit_group;" ::: "memory");
    };

    float acc[4][8][4];
    #pragma unroll
    for (int i = 0; i < 4; i++)
        #pragma unroll
        for (int j = 0; j < 8; j++)
            #pragma unroll
            for (int q = 0; q < 4; q++) acc[i][j][q] = 0.f;

    load_stage(0, 0);
    load_stage(1, 1);

    for (int c = 0; c < nck; c++) {
        if (c == nck - 1) asm volatile("cp.async.wait_group 0;" ::: "memory");
        else              asm volatile("cp.async.wait_group 1;" ::: "memory");
        __syncthreads();
        if (c + 2 < nck) load_stage((c + 2) % 3, c + 2);
        const uint32_t at0 = sb0 + (uint32_t)(c % 3) * STB;
        const uint32_t bt0 = at0 + NS * TBA;
        #pragma unroll
        for (int ks = 0; ks < 2; ks++) {
            uint32_t aF[NS][4][4];
            #pragma unroll
            for (int t = 0; t < NS; t++)
                #pragma unroll
                for (int i = 0; i < 4; i++) {
                    const int row = wm * 64 + i * 16 + (lane & 15);
                    ldsm4(aF[t][i], at0 + t * TBA + row * 80 + (ks * 16 + (lane >> 4) * 8) * 2);
                }
            #pragma unroll
            for (int tb = 0; tb < NS; tb++) {
                uint32_t bF[4][4];
                #pragma unroll
                for (int jp = 0; jp < 4; jp++) {
                    const int rn = wn * 64 + jp * 16 + (lane & 7) + ((lane >> 4) << 3);
                    ldsm4(bF[jp], bt0 + tb * TBB + rn * 80 + (ks * 16 + ((lane >> 3) & 1) * 8) * 2);
                }
                #pragma unroll
                for (int ta = 0; ta < NS; ta++) {
                    if (NS == 2 && ta == 1 && tb == 1) continue;   // 3-pair
                    #pragma unroll
                    for (int i = 0; i < 4; i++)
                        #pragma unroll
                        for (int j = 0; j < 8; j++)
                            mma16816(acc[i][j], aF[ta][i],
                                     bF[j >> 1][(j & 1) * 2], bF[j >> 1][(j & 1) * 2 + 1]);
                }
            }
        }
    }

    const int er = lane >> 2, ec = (lane & 3) * 2;
    #pragma unroll
    for (int i = 0; i < 4; i++) {
        const int row = brow + wm * 64 + i * 16 + er;
        #pragma unroll
        for (int j = 0; j < 8; j++) {
            const int col = bcol + wn * 64 + j * 8 + ec;
            const float bz0 = bias[col], bz1 = bias[col + 1];
            float* c0 = C + (size_t)row * ldC + col;
            float* c1 = C + (size_t)(row + 8) * ldC + col;
            c0[0] = acc[i][j][0] + bz0; c0[1] = acc[i][j][1] + bz1;
            c1[0] = acc[i][j][2] + bz0; c1[1] = acc[i][j][3] + bz1;
        }
    }
}

// ======== 128x128-tile split GEMM (R4-proven 2x4 warp map), 3-stage, 1 sync ========
#define TBA8 10240u   // 128 rows x 80 B
template <int NS>
__global__ __launch_bounds__(256, 1)
void gemm_sp128(const __half* a0, const __half* a1,
                const __half* b0, const __half* b1,
                const float* __restrict__ bias, float* __restrict__ C,
                int ldb, int ldC, int nck)
{
    extern __shared__ char dsm[];
    const uint32_t sb0 = smem_u32(dsm);
    const int tid = threadIdx.x, lane = tid & 31, warp = tid >> 5;
    const int wm = warp >> 2, wn = warp & 3;        // 2 x 4
    const int brow = blockIdx.y * 128, bcol = blockIdx.x * 128;
    constexpr uint32_t STB = NS * (TBA8 + TBB);
    const __half* As[2] = {a0, a1};
    const __half* Bs[2] = {b0, b1};

    auto load_stage = [&](int slot, int kc) {
        const uint32_t st = sb0 + (uint32_t)slot * STB;
        #pragma unroll
        for (int t = 0; t < NS; t++) {
            const __half* ga = As[t] + (size_t)brow * 512 + kc * 32;
            const __half* gb = Bs[t] + (size_t)bcol * ldb + kc * 32;
            #pragma unroll
            for (int r = 0; r < 2; r++) {
                const int lin = r * 256 + tid, row = lin >> 2, c16 = lin & 3;
                cpa16(st + t * TBA8 + row * 80 + c16 * 16, ga + (size_t)row * 512 + c16 * 8);
                cpa16(st + NS * TBA8 + t * TBB + row * 80 + c16 * 16, gb + (size_t)row * ldb + c16 * 8);
            }
        }
        asm volatile("cp.async.commit_group;" ::: "memory");
    };

    float acc[4][4][4];
    #pragma unroll
    for (int i = 0; i < 4; i++)
        #pragma unroll
        for (int j = 0; j < 4; j++)
            #pragma unroll
            for (int q = 0; q < 4; q++) acc[i][j][q] = 0.f;

    load_stage(0, 0);
    load_stage(1, 1);

    for (int c = 0; c < nck; c++) {
        if (c == nck - 1) asm volatile("cp.async.wait_group 0;" ::: "memory");
        else              asm volatile("cp.async.wait_group 1;" ::: "memory");
        __syncthreads();
        if (c + 2 < nck) load_stage((c + 2) % 3, c + 2);
        const uint32_t at0 = sb0 + (uint32_t)(c % 3) * STB;
        const uint32_t bt0 = at0 + NS * TBA8;
        #pragma unroll
        for (int ks = 0; ks < 2; ks++) {
            uint32_t aF[NS][4][4];
            #pragma unroll
            for (int t = 0; t < NS; t++)
                #pragma unroll
                for (int i = 0; i < 4; i++) {
                    const int row = wm * 64 + i * 16 + (lane & 15);
                    ldsm4(aF[t][i], at0 + t * TBA8 + row * 80 + (ks * 16 + (lane >> 4) * 8) * 2);
                }
            #pragma unroll
            for (int tb = 0; tb < NS; tb++) {
                uint32_t bF[2][4];
                #pragma unroll
                for (int jp = 0; jp < 2; jp++) {
                    const int rn = wn * 32 + jp * 16 + (lane & 7) + ((lane >> 4) << 3);
                    ldsm4(bF[jp], bt0 + tb * TBB + rn * 80 + (ks * 16 + ((lane >> 3) & 1) * 8) * 2);
                }
                #pragma unroll
                for (int ta = 0; ta < NS; ta++) {
                    if (NS == 2 && ta == 1 && tb == 1) continue;
                    #pragma unroll
                    for (int i = 0; i < 4; i++)
                        #pragma unroll
                        for (int j = 0; j < 4; j++)
                            mma16816(acc[i][j], aF[ta][i],
                                     bF[j >> 1][(j & 1) * 2], bF[j >> 1][(j & 1) * 2 + 1]);
                }
            }
        }
    }

    const int er = lane >> 2, ec = (lane & 3) * 2;
    #pragma unroll
    for (int i = 0; i < 4; i++) {
        const int row = brow + wm * 64 + i * 16 + er;
        #pragma unroll
        for (int j = 0; j < 4; j++) {
            const int col = bcol + wn * 32 + j * 8 + ec;
            const float bz0 = bias[col], bz1 = bias[col + 1];
            float* c0 = C + (size_t)row * ldC + col;
            float* c1 = C + (size_t)(row + 8) * ldC + col;
            c0[0] = acc[i][j][0] + bz0; c0[1] = acc[i][j][1] + bz1;
            c1[0] = acc[i][j][2] + bz0; c1[1] = acc[i][j][3] + bz1;
        }
    }
}

// ===== fused gate GEMM + LSTM (256-tile, interleaved n=4h+g, M2 gather), 3-stage =====
template <int NS>
__global__ __launch_bounds__(256, 1)
void gemm_gate(const __half* a0, const __half* a1,
               const __half* b0, const __half* b1,
               const float* __restrict__ biasI, const float* __restrict__ M2I,
               const int* __restrict__ imax, const float* __restrict__ zval,
               float* __restrict__ cx, __half* wo1, __half* wo2)
{
    extern __shared__ char dsm[];
    const uint32_t sb0 = smem_u32(dsm);
    const int tid = threadIdx.x, lane = tid & 31, warp = tid >> 5;
    const int wm = warp >> 1, wn = warp & 1;
    const int brow = blockIdx.y * 256, bcol = blockIdx.x * 128;
    constexpr uint32_t STB = NS * (TBA + TBB);
    const __half* As[2] = {a0, a1};
    const __half* Bs[2] = {b0, b1};
    const int nck = 16;

    auto load_stage = [&](int slot, int kc) {
        const uint32_t st = sb0 + (uint32_t)slot * STB;
        #pragma unroll
        for (int t = 0; t < NS; t++) {
            const __half* ga = As[t] + (size_t)brow * 512 + kc * 32;
            #pragma unroll
            for (int r = 0; r < 4; r++) {
                const int lin = r * 256 + tid, row = lin >> 2, c16 = lin & 3;
                cpa16(st + t * TBA + row * 80 + c16 * 16, ga + (size_t)row * 512 + c16 * 8);
            }
            const __half* gb = Bs[t] + (size_t)bcol * 512 + kc * 32;
            #pragma unroll
            for (int r = 0; r < 2; r++) {
                const int lin = r * 256 + tid, row = lin >> 2, c16 = lin & 3;
                cpa16(st + NS * TBA + t * TBB + row * 80 + c16 * 16, gb + (size_t)row * 512 + c16 * 8);
            }
        }
        asm volatile("cp.async.commit_group;" ::: "memory");
    };

    float acc[4][8][4];
    #pragma unroll
    for (int i = 0; i < 4; i++)
        #pragma unroll
        for (int j = 0; j < 8; j++)
            #pragma unroll
            for (int q = 0; q < 4; q++) acc[i][j][q] = 0.f;

    load_stage(0, 0);
    load_stage(1, 1);

    for (int c = 0; c < nck; c++) {
        if (c == nck - 1) asm volatile("cp.async.wait_group 0;" ::: "memory");
        else              asm volatile("cp.async.wait_group 1;" ::: "memory");
        __syncthreads();
        if (c + 2 < nck) load_stage((c + 2) % 3, c + 2);
        const uint32_t at0 = sb0 + (uint32_t)(c % 3) * STB;
        const uint32_t bt0 = at0 + NS * TBA;
        #pragma unroll
        for (int ks = 0; ks < 2; ks++) {
            uint32_t aF[NS][4][4];
            #pragma unroll
            for (int t = 0; t < NS; t++)
                #pragma unroll
                for (int i = 0; i < 4; i++) {
                    const int row = wm * 64 + i * 16 + (lane & 15);
                    ldsm4(aF[t][i], at0 + t * TBA + row * 80 + (ks * 16 + (lane >> 4) * 8) * 2);
                }
            #pragma unroll
            for (int tb = 0; tb < NS; tb++) {
                uint32_t bF[4][4];
                #pragma unroll
                for (int jp = 0; jp < 4; jp++) {
                    const int rn = wn * 64 + jp * 16 + (lane & 7) + ((lane >> 4) << 3);
                    ldsm4(bF[jp], bt0 + tb * TBB + rn * 80 + (ks * 16 + ((lane >> 3) & 1) * 8) * 2);
                }
                #pragma unroll
                for (int ta = 0; ta < NS; ta++) {
                    if (NS == 2 && ta == 1 && tb == 1) continue;
                    #pragma unroll
                    for (int i = 0; i < 4; i++)
                        #pragma unroll
                        for (int j = 0; j < 8; j++)
                            mma16816(acc[i][j], aF[ta][i],
                                     bF[j >> 1][(j & 1) * 2], bF[j >> 1][(j & 1) * 2 + 1]);
                }
            }
        }
    }

    // fused LSTM epilogue (R11-proven)
    const int er = lane >> 2, ec = (lane & 3) * 2;
    #pragma unroll
    for (int i = 0; i < 4; i++) {
        const int r0 = brow + wm * 64 + i * 16 + er;
        const int r1 = r0 + 8;
        const float zv0 = zval[r0], zv1 = zval[r1];
        const float* m0 = M2I + (size_t)imax[r0] * 2048;
        const float* m1 = M2I + (size_t)imax[r1] * 2048;
        #pragma unroll
        for (int j = 0; j < 8; j++) {
            const int col = bcol + wn * 64 + j * 8 + ec;
            const float bz0 = biasI[col], bz1 = biasI[col + 1];
            const float v0 = acc[i][j][0] + bz0 + zv0 * m0[col];
            const float v1 = acc[i][j][1] + bz1 + zv0 * m0[col + 1];
            const float v2 = acc[i][j][2] + bz0 + zv1 * m1[col];
            const float v3 = acc[i][j][3] + bz1 + zv1 * m1[col + 1];
            const float p0 = __shfl_xor_sync(0xffffffffu, v0, 1);
            const float p1 = __shfl_xor_sync(0xffffffffu, v1, 1);
            const float p2 = __shfl_xor_sync(0xffffffffu, v2, 1);
            const float p3 = __shfl_xor_sync(0xffffffffu, v3, 1);
            const int h = col >> 2;
            int rw; float gi, gf, gg, go;
            if ((lane & 1) == 0) { rw = r0; gi = v0; gf = v1; gg = p0; go = p1; }
            else                 { rw = r1; gi = p2; gf = p3; gg = v2; go = v3; }
            const size_t idx = (size_t)rw * 512 + h;
            const float cnew = sigf(gf) * cx[idx] + sigf(gi) * tanhf(gg);
            cx[idx] = cnew;
            const float hv = sigf(go) * tanhf(cnew);
            if (NS == 2) split2h(hv, wo1, wo2, idx);
            else         wo1[idx] = __float2half_rn(hv);
        }
    }
}

// ---------------- softmax + straight-through (proven) ----------------
__global__ __launch_bounds__(256)
void softmax_st(const float* __restrict__ logits, const float* __restrict__ gumbel, int t,
                float* __restrict__ onehot, float* __restrict__ messages,
                int* __restrict__ imaxO, float* __restrict__ zvalO)
{
    const int b = blockIdx.x, tid = threadIdx.x;
    const float* pre = logits + (size_t)b * (L_ * D_) + (size_t)t * D_;
    const float* gm = gumbel + ((size_t)t * B_ + b) * D_;
    float y[4]; float vmax = -INFINITY; int imax = 0;
    #pragma unroll
    for (int q = 0; q < 4; q++) {
        const int d = tid + q * 256;
        y[q] = pre[d] + gm[d];
        if (y[q] > vmax) { vmax = y[q]; imax = d; }
    }
    __shared__ float sv[256]; __shared__ int si[256]; __shared__ float ss[256];
    sv[tid] = vmax; si[tid] = imax;
    __syncthreads();
    for (int s = 128; s > 0; s >>= 1) {
        if (tid < s) {
            const float ov = sv[tid + s]; const int oi = si[tid + s];
            if (ov > sv[tid] || (ov == sv[tid] && oi < si[tid])) { sv[tid] = ov; si[tid] = oi; }
        }
        __syncthreads();
    }
    vmax = sv[0]; imax = si[0];
    float ls = 0.f;
    #pragma unroll
    for (int q = 0; q < 4; q++) ls += expf(y[q] - vmax);
    ss[tid] = ls;
    __syncthreads();
    for (int s = 128; s > 0; s >>= 1) { if (tid < s) ss[tid] += ss[tid + s]; __syncthreads(); }
    const float sm = 1.f / ss[0];
    const float zval = sm + (1.f - sm);
    float* oh = onehot + (size_t)b * (L_ * D_) + (size_t)t * D_;
    #pragma unroll
    for (int q = 0; q < 4; q++) { const int d = tid + q * 256; oh[d] = (d == imax) ? zval : 0.f; }
    if (tid == 0) {
        messages[(size_t)b * L_ + t] = (float)imax;
        imaxO[b] = imax;
        zvalO[b] = zval;
    }
}

// ---------------- consolidated prep (R11-proven) ----------------
__global__ void prep_all(const float* __restrict__ eWih, const float* __restrict__ eWhh,
                         const float* __restrict__ dWih, const float* __restrict__ dWhh,
                         const float* __restrict__ t2h_W, const float* __restrict__ h2t_W,
                         const float* __restrict__ in_W, const float* __restrict__ out_W,
                         const float* __restrict__ x,
                         __half* WhE1, __half* WhE2, __half* WiE1, __half* WiE2,
                         __half* WhD1, __half* WiD1, __half* WiD2,
                         __half* t2hT1, __half* t2hT2, __half* h2t1, __half* h2t2,
                         __half* inW1, __half* inW2, __half* outW1,
                         __half* x1, __half* x2,
                         __half* hxA, __half* hxB, __half* hx21,
                         float* cx2, float* bz, float* zv0, int* im0)
{
    int i = blockIdx.x * 256 + threadIdx.x;
    if (i < 1048576) {
        const int n = i >> 9, k = i & 511, r = ((n & 3) << 9) + (n >> 2);
        split2h(eWhh[(size_t)r * 512 + k], WhE1, WhE2, i);
        return;
    }
    i -= 1048576;
    if (i < 1048576) {
        const int n = i >> 9, k = i & 511, r = ((n & 3) << 9) + (n >> 2);
        split2h(eWih[(size_t)r * 512 + k], WiE1, WiE2, i);
        return;
    }
    i -= 1048576;
    if (i < 1048576) {
        const int n = i >> 9, k = i & 511, r = ((n & 3) << 9) + (n >> 2);
        WhD1[i] = __float2half_rn(dWhh[(size_t)r * 512 + k]);
        return;
    }
    i -= 1048576;
    if (i < 1048576) {
        const int n = i >> 9, k = i & 511, r = ((n & 3) << 9) + (n >> 2);
        split2h(dWih[(size_t)r * 512 + k], WiD1, WiD2, i);
        return;
    }
    i -= 1048576;
    if (i < 524288) {
        const int d = i >> 9, h = i & 511;
        split2h(t2h_W[(size_t)h * 1024 + d], t2hT1, t2hT2, i);
        return;
    }
    i -= 524288;
    if (i < 524288) { split2h(h2t_W[i], h2t1, h2t2, i); return; }
    i -= 524288;
    if (i < 262144) { split2h(in_W[i], inW1, inW2, i); return; }
    i -= 262144;
    if (i < 262144) { outW1[i] = __float2half_rn(out_W[i]); return; }
    i -= 262144;
    if (i < 1048576) { split2h(x[i], x1, x2, i); return; }
    i -= 1048576;
    if (i < 1048576) {
        const __half z = __float2half_rn(0.f);
        hxA[i] = z; hxB[i] = z; hx21[i] = z; cx2[i] = 0.f;
        if (i < 2048) { bz[i] = 0.f; }
        if (i < B_) { zv0[i] = 0.f; im0[i] = 0; }
    }
}

__global__ void bias_fold2(const float* __restrict__ eWih, const float* __restrict__ ebih,
                           const float* __restrict__ ebhh,
                           const float* __restrict__ dWih, const float* __restrict__ dbih,
                           const float* __restrict__ dbhh,
                           const float* __restrict__ t2hb,
                           float* __restrict__ b0e, float* __restrict__ b2e,
                           float* __restrict__ b2d)
{
    const int tid = blockIdx.x * 256 + threadIdx.x;
    if (tid < 2048) {
        const int n = tid, r = ((n & 3) << 9) + (n >> 2);
        const float s = ebih[r] + ebhh[r];
        float acc = 0.f;
        const float* wr = eWih + (size_t)r * 512;
        for (int k = 0; k < 512; k++) acc += t2hb[k] * wr[k];
        b0e[n] = s; b2e[n] = s + acc;
    } else if (tid < 4096) {
        const int n = tid - 2048, r = ((n & 3) << 9) + (n >> 2);
        const float s = dbih[r] + dbhh[r];
        float acc = 0.f;
        const float* wr = dWih + (size_t)r * 512;
        for (int k = 0; k < 512; k++) acc += t2hb[k] * wr[k];
        b2d[n] = s + acc;
    }
}

// ---------------- host ----------------
#define SYM(p, s) cudaGetSymbolAddress((void**)&p, s)

extern "C" void kernel_launch(void* const* d_in, const int* in_sizes, int n_in,
                              void* d_out, int out_size)
{
    const float* x = (const float*)d_in[0];
    const float* gumbel = (const float*)d_in[1];
    const float* in_W = (const float*)d_in[2];
    const float* in_b = (const float*)d_in[3];
    const float* out_W = (const float*)d_in[4];
    const float* out_b = (const float*)d_in[5];
    const float* eWih = (const float*)d_in[6];
    const float* eWhh = (const float*)d_in[7];
    const float* ebih = (const float*)d_in[8];
    const float* ebhh = (const float*)d_in[9];
    const float* dWih = (const float*)d_in[10];
    const float* dWhh = (const float*)d_in[11];
    const float* dbih = (const float*)d_in[12];
    const float* dbhh = (const float*)d_in[13];
    const float* h2t_W = (const float*)d_in[14];
    const float* h2t_b = (const float*)d_in[15];
    const float* t2h_W = (const float*)d_in[16];
    const float* t2h_b = (const float*)d_in[17];

    float* out = (float*)d_out;
    float* o_recon = out;
    float* o_oh = out + (size_t)B_ * O_;
    float* o_lg = o_oh + (size_t)B_ * L_ * D_;
    float* o_msg = o_lg + (size_t)B_ * L_ * D_;

    float *cx, *cx2, *M2e, *M2d, *b0e, *b2e, *b2d, *bz, *zvalL;
    int* imaxL;
    __half *WhE1, *WhE2, *WiE1, *WiE2, *WhD1, *WiD1, *WiD2;
    __half *t2hT1, *t2hT2, *h2t1, *h2t2, *inW1, *inW2, *outW1;
    __half *x1, *x2, *hxA, *hxB, *hxC, *hxD, *hx21, *hx21b;
    SYM(cx, g_cx); SYM(cx2, g_cx2);
    SYM(M2e, g_M2e); SYM(M2d, g_M2d);
    SYM(b0e, g_b0e); SYM(b2e, g_b2e); SYM(b2d, g_b2d); SYM(bz, g_bz);
    SYM(zvalL, g_zvalL); SYM(imaxL, g_imaxL);
    SYM(WhE1, g_WhE1); SYM(WhE2, g_WhE2); SYM(WiE1, g_WiE1); SYM(WiE2, g_WiE2);
    SYM(WhD1, g_WhD1); SYM(WiD1, g_WiD1); SYM(WiD2, g_WiD2);
    SYM(t2hT1, g_t2hT1); SYM(t2hT2, g_t2hT2); SYM(h2t1, g_h2t1); SYM(h2t2, g_h2t2);
    SYM(inW1, g_inW1); SYM(inW2, g_inW2); SYM(outW1, g_outW1);
    SYM(x1, g_x1); SYM(x2, g_x2);
    SYM(hxA, g_hxA); SYM(hxB, g_hxB); SYM(hxC, g_hxC); SYM(hxD, g_hxD);
    SYM(hx21, g_hx21); SYM(hx21b, g_hx21b);

    const int S2  = 3 * 2 * (TBA + TBB);    // 184320
    const int S1  = 3 * 1 * (TBA + TBB);    // 92160
    const int T2  = 3 * 2 * (TBA8 + TBB);   // 122880
    const int T1  = 3 * 1 * (TBA8 + TBB);   // 61440
    cudaFuncSetAttribute(gemm_sp<2>, cudaFuncAttributeMaxDynamicSharedMemorySize, S2);
    cudaFuncSetAttribute(gemm_sp<1>, cudaFuncAttributeMaxDynamicSharedMemorySize, S1);
    cudaFuncSetAttribute(gemm_sp128<2>, cudaFuncAttributeMaxDynamicSharedMemorySize, T2);
    cudaFuncSetAttribute(gemm_sp128<1>, cudaFuncAttributeMaxDynamicSharedMemorySize, T1);
    cudaFuncSetAttribute(gemm_gate<2>, cudaFuncAttributeMaxDynamicSharedMemorySize, S2);
    cudaFuncSetAttribute(gemm_gate<1>, cudaFuncAttributeMaxDynamicSharedMemorySize, S1);

    prep_all<<<30720, 256>>>(eWih, eWhh, dWih, dWhh, t2h_W, h2t_W, in_W, out_W, x,
                             WhE1, WhE2, WiE1, WiE2, WhD1, WiD1, WiD2,
                             t2hT1, t2hT2, h2t1, h2t2, inW1, inW2, outW1,
                             x1, x2, hxA, hxB, hx21, cx2, bz, zvalL, imaxL);
    bias_fold2<<<16, 256>>>(eWih, ebih, ebhh, dWih, dbih, dbhh, t2h_b, b0e, b2e, b2d);
    // M2eI / M2dI: 128-tile -> 128 CTAs each
    gemm_sp128<2><<<dim3(16, 8), 256, T2>>>(t2hT1, t2hT2, WiE1, WiE2, bz, M2e, 512, 2048, 16);
    gemm_sp128<2><<<dim3(16, 8), 256, T2>>>(t2hT1, t2hT2, WiD1, WiD2, bz, M2d, 512, 2048, 16);
    // cx = x @ in_W^T + in_b
    gemm_sp128<2><<<dim3(4, 16), 256, T2>>>(x1, x2, inW1, inW2, in_b, cx, 512, 512, 16);

    // ---- encoder (launch 5 = first fused gate GEMM -> ncu target) ----
    for (int t = 0; t < L_; t++) {
        __half *hr1 = (t & 1) ? hxC : hxA, *hr2 = (t & 1) ? hxD : hxB;
        __half *hw1 = (t & 1) ? hxA : hxC, *hw2 = (t & 1) ? hxB : hxD;
        gemm_gate<2><<<dim3(16, 8), 256, S2>>>(hr1, hr2, WhE1, WhE2,
            (t == 0) ? b0e : b2e, M2e, imaxL + (size_t)t * B_, zvalL + (size_t)t * B_,
            cx, hw1, hw2);
        gemm_sp128<2><<<dim3(8, 16), 256, T2>>>(hw1, hw2, h2t1, h2t2, h2t_b,
            o_lg + (size_t)t * D_, 512, L_ * D_, 16);
        softmax_st<<<B_, 256>>>(o_lg, gumbel, t, o_oh, o_msg,
            imaxL + (size_t)(t + 1) * B_, zvalL + (size_t)(t + 1) * B_);
    }

    // ---- decoder ----
    for (int t = 0; t < L_; t++) {
        __half* hr = (t & 1) ? hx21b : hx21;
        __half* hw = (t & 1) ? hx21 : hx21b;
        gemm_gate<1><<<dim3(16, 8), 256, S1>>>(hr, hr, WhD1, WhD1, b2d, M2d,
            imaxL + (size_t)(t + 1) * B_, zvalL + (size_t)(t + 1) * B_,
            cx2, hw, nullptr);
    }
    gemm_sp128<1><<<dim3(4, 16), 256, T1>>>(hx21, hx21, outW1, outW1, out_b, o_recon,
                                            512, 512, 16);
}

// round 14
// speedup vs baseline: 1.7141x; 1.2182x over previous
#include <cuda_runtime.h>
#include <cuda_fp16.h>
#include <math.h>
#include <stdint.h>
#include <stddef.h>

#define B_ 2048
#define H_ 512
#define L_ 32
#define D_ 1024
#define O_ 512

// ---------------- device scratch ----------------
__device__ float g_cx[B_ * H_];
__device__ float g_cx2[B_ * H_];
__device__ float g_M2e[D_ * 2048];   // interleaved cols
__device__ float g_M2d[D_ * 2048];   // interleaved cols
__device__ float g_b0e[2048], g_b2e[2048], g_b2d[2048], g_bz[2048];
__device__ __half g_WhE1[2048 * 512], g_WhE2[2048 * 512];   // interleaved rows
__device__ __half g_WiE1[2048 * 512], g_WiE2[2048 * 512];   // interleaved rows
__device__ __half g_WhD1[2048 * 512];                        // interleaved rows
__device__ __half g_WiD1[2048 * 512], g_WiD2[2048 * 512];   // interleaved rows
__device__ __half g_t2hT1[D_ * 512], g_t2hT2[D_ * 512];
__device__ __half g_h2t1[D_ * 512], g_h2t2[D_ * 512];
__device__ __half g_inW1[H_ * 512], g_inW2[H_ * 512];
__device__ __half g_outW1[O_ * 512];
__device__ __half g_x1[B_ * 512], g_x2[B_ * 512];
__device__ __half g_hxA[B_ * 512], g_hxB[B_ * 512];
__device__ __half g_hxC[B_ * 512], g_hxD[B_ * 512];
__device__ __half g_hx21[B_ * 512], g_hx21b[B_ * 512];
__device__ int   g_imaxL[(L_ + 1) * B_];
__device__ float g_zvalL[(L_ + 1) * B_];

// ---------------- PTX helpers ----------------
__device__ __forceinline__ uint32_t smem_u32(const void* p) {
    uint32_t a;
    asm("{ .reg .u64 t; cvta.to.shared.u64 t, %1; cvt.u32.u64 %0, t; }" : "=r"(a) : "l"(p));
    return a;
}
__device__ __forceinline__ void cpa16(uint32_t sa, const void* g) {
    asm volatile("cp.async.cg.shared.global [%0], [%1], 16;" :: "r"(sa), "l"(g));
}
__device__ __forceinline__ void ldsm4(uint32_t* r, uint32_t addr) {
    asm volatile("ldmatrix.sync.aligned.m8n8.x4.shared.b16 {%0,%1,%2,%3}, [%4];"
        : "=r"(r[0]), "=r"(r[1]), "=r"(r[2]), "=r"(r[3]) : "r"(addr));
}
__device__ __forceinline__ void mma16816(float* c, const uint32_t* a, uint32_t b0, uint32_t b1) {
    asm volatile("mma.sync.aligned.m16n8k16.row.col.f32.f16.f16.f32 "
        "{%0,%1,%2,%3}, {%4,%5,%6,%7}, {%8,%9}, {%0,%1,%2,%3};"
        : "+f"(c[0]), "+f"(c[1]), "+f"(c[2]), "+f"(c[3])
        : "r"(a[0]), "r"(a[1]), "r"(a[2]), "r"(a[3]), "r"(b0), "r"(b1));
}
__device__ __forceinline__ float sigf(float x) { return 1.f / (1.f + expf(-x)); }
__device__ __forceinline__ void split2h(float v, __half* p1, __half* p2, size_t i) {
    __half h1 = __float2half_rn(v);
    p1[i] = h1; p2[i] = __float2half_rn(v - __half2float(h1));
}

// Unpadded 64B rows + additive chunk swizzle: chunk slot = (c + (row>>1)) & 3.
// 16B-aligned cp.async targets; ldmatrix phases conflict-free (see analysis).
#define TBK 8192u
__device__ __forceinline__ uint32_t swz(int row, int chunk) {
    return (uint32_t)(row * 64 + (((chunk + (row >> 1)) & 3) * 16));
}

// ======== 128x128-tile split GEMM, 3-stage, 1 sync/chunk, 2 CTAs/SM ========
template <int NS>
__global__ __launch_bounds__(256, 2)
void gemm128(const __half* a0, const __half* a1,
             const __half* b0, const __half* b1,
             const float* __restrict__ bias, float* __restrict__ C,
             int ldb, int ldC, int nck)
{
    extern __shared__ char dsm[];
    const uint32_t sb0 = smem_u32(dsm);
    const int tid = threadIdx.x, lane = tid & 31, warp = tid >> 5;
    const int wm = warp >> 2, wn = warp & 3;        // 2 x 4
    const int brow = blockIdx.y * 128, bcol = blockIdx.x * 128;
    constexpr uint32_t STB = NS * (2u * TBK);
    const __half* As[2] = {a0, a1};
    const __half* Bs[2] = {b0, b1};

    auto load_stage = [&](int slot, int kc) {
        const uint32_t st = sb0 + (uint32_t)slot * STB;
        #pragma unroll
        for (int t = 0; t < NS; t++) {
            const __half* ga = As[t] + (size_t)brow * 512 + kc * 32;
            const __half* gb = Bs[t] + (size_t)bcol * ldb + kc * 32;
            #pragma unroll
            for (int r = 0; r < 2; r++) {
                const int lin = r * 256 + tid, row = lin >> 2, c16 = lin & 3;
                cpa16(st + t * TBK + swz(row, c16), ga + (size_t)row * 512 + c16 * 8);
                cpa16(st + NS * TBK + t * TBK + swz(row, c16), gb + (size_t)row * ldb + c16 * 8);
            }
        }
        asm volatile("cp.async.commit_group;" ::: "memory");
    };

    float acc[4][4][4];
    #pragma unroll
    for (int i = 0; i < 4; i++)
        #pragma unroll
        for (int j = 0; j < 4; j++)
            #pragma unroll
            for (int q = 0; q < 4; q++) acc[i][j][q] = 0.f;

    load_stage(0, 0);
    load_stage(1, 1);

    for (int c = 0; c < nck; c++) {
        if (c == nck - 1) asm volatile("cp.async.wait_group 0;" ::: "memory");
        else              asm volatile("cp.async.wait_group 1;" ::: "memory");
        __syncthreads();
        if (c + 2 < nck) load_stage((c + 2) % 3, c + 2);
        const uint32_t at0 = sb0 + (uint32_t)(c % 3) * STB;
        const uint32_t bt0 = at0 + NS * TBK;
        #pragma unroll
        for (int ks = 0; ks < 2; ks++) {
            uint32_t aF[NS][4][4];
            #pragma unroll
            for (int t = 0; t < NS; t++)
                #pragma unroll
                for (int i = 0; i < 4; i++) {
                    const int row = wm * 64 + i * 16 + (lane & 15);
                    ldsm4(aF[t][i], at0 + t * TBK + swz(row, ks * 2 + (lane >> 4)));
                }
            #pragma unroll
            for (int tb = 0; tb < NS; tb++) {
                uint32_t bF[2][4];
                #pragma unroll
                for (int jp = 0; jp < 2; jp++) {
                    const int rn = wn * 32 + jp * 16 + (lane & 7) + ((lane >> 4) << 3);
                    ldsm4(bF[jp], bt0 + tb * TBK + swz(rn, ks * 2 + ((lane >> 3) & 1)));
                }
                #pragma unroll
                for (int ta = 0; ta < NS; ta++) {
                    if (NS == 2 && ta == 1 && tb == 1) continue;   // 3-pair
                    #pragma unroll
                    for (int i = 0; i < 4; i++)
                        #pragma unroll
                        for (int j = 0; j < 4; j++)
                            mma16816(acc[i][j], aF[ta][i],
                                     bF[j >> 1][(j & 1) * 2], bF[j >> 1][(j & 1) * 2 + 1]);
                }
            }
        }
    }

    const int er = lane >> 2, ec = (lane & 3) * 2;
    #pragma unroll
    for (int i = 0; i < 4; i++) {
        const int row = brow + wm * 64 + i * 16 + er;
        #pragma unroll
        for (int j = 0; j < 4; j++) {
            const int col = bcol + wn * 32 + j * 8 + ec;
            const float bz0 = bias[col], bz1 = bias[col + 1];
            float* c0 = C + (size_t)row * ldC + col;
            float* c1 = C + (size_t)(row + 8) * ldC + col;
            c0[0] = acc[i][j][0] + bz0; c0[1] = acc[i][j][1] + bz1;
            c1[0] = acc[i][j][2] + bz0; c1[1] = acc[i][j][3] + bz1;
        }
    }
}

// ===== fused gate GEMM + LSTM (128-tile, interleaved n=4h+g, M2 gather), 2 CTAs/SM =====
template <int NS>
__global__ __launch_bounds__(256, 2)
void gate128(const __half* a0, const __half* a1,
             const __half* b0, const __half* b1,
             const float* __restrict__ biasI, const float* __restrict__ M2I,
             const int* __restrict__ imax, const float* __restrict__ zval,
             float* __restrict__ cx, __half* wo1, __half* wo2)
{
    extern __shared__ char dsm[];
    const uint32_t sb0 = smem_u32(dsm);
    const int tid = threadIdx.x, lane = tid & 31, warp = tid >> 5;
    const int wm = warp >> 2, wn = warp & 3;
    const int brow = blockIdx.y * 128, bcol = blockIdx.x * 128;
    constexpr uint32_t STB = NS * (2u * TBK);
    const __half* As[2] = {a0, a1};
    const __half* Bs[2] = {b0, b1};
    const int nck = 16;

    auto load_stage = [&](int slot, int kc) {
        const uint32_t st = sb0 + (uint32_t)slot * STB;
        #pragma unroll
        for (int t = 0; t < NS; t++) {
            const __half* ga = As[t] + (size_t)brow * 512 + kc * 32;
            const __half* gb = Bs[t] + (size_t)bcol * 512 + kc * 32;
            #pragma unroll
            for (int r = 0; r < 2; r++) {
                const int lin = r * 256 + tid, row = lin >> 2, c16 = lin & 3;
                cpa16(st + t * TBK + swz(row, c16), ga + (size_t)row * 512 + c16 * 8);
                cpa16(st + NS * TBK + t * TBK + swz(row, c16), gb + (size_t)row * 512 + c16 * 8);
            }
        }
        asm volatile("cp.async.commit_group;" ::: "memory");
    };

    float acc[4][4][4];
    #pragma unroll
    for (int i = 0; i < 4; i++)
        #pragma unroll
        for (int j = 0; j < 4; j++)
            #pragma unroll
            for (int q = 0; q < 4; q++) acc[i][j][q] = 0.f;

    load_stage(0, 0);
    load_stage(1, 1);

    for (int c = 0; c < nck; c++) {
        if (c == nck - 1) asm volatile("cp.async.wait_group 0;" ::: "memory");
        else              asm volatile("cp.async.wait_group 1;" ::: "memory");
        __syncthreads();
        if (c + 2 < nck) load_stage((c + 2) % 3, c + 2);
        const uint32_t at0 = sb0 + (uint32_t)(c % 3) * STB;
        const uint32_t bt0 = at0 + NS * TBK;
        #pragma unroll
        for (int ks = 0; ks < 2; ks++) {
            uint32_t aF[NS][4][4];
            #pragma unroll
            for (int t = 0; t < NS; t++)
                #pragma unroll
                for (int i = 0; i < 4; i++) {
                    const int row = wm * 64 + i * 16 + (lane & 15);
                    ldsm4(aF[t][i], at0 + t * TBK + swz(row, ks * 2 + (lane >> 4)));
                }
            #pragma unroll
            for (int tb = 0; tb < NS; tb++) {
                uint32_t bF[2][4];
                #pragma unroll
                for (int jp = 0; jp < 2; jp++) {
                    const int rn = wn * 32 + jp * 16 + (lane & 7) + ((lane >> 4) << 3);
                    ldsm4(bF[jp], bt0 + tb * TBK + swz(rn, ks * 2 + ((lane >> 3) & 1)));
                }
                #pragma unroll
                for (int ta = 0; ta < NS; ta++) {
                    if (NS == 2 && ta == 1 && tb == 1) continue;
                    #pragma unroll
                    for (int i = 0; i < 4; i++)
                        #pragma unroll
                        for (int j = 0; j < 4; j++)
                            mma16816(acc[i][j], aF[ta][i],
                                     bF[j >> 1][(j & 1) * 2], bF[j >> 1][(j & 1) * 2 + 1]);
                }
            }
        }
    }

    // fused LSTM epilogue (proven lane-pair algebra; 2x4 map)
    const int er = lane >> 2, ec = (lane & 3) * 2;
    #pragma unroll
    for (int i = 0; i < 4; i++) {
        const int r0 = brow + wm * 64 + i * 16 + er;
        const int r1 = r0 + 8;
        const float zv0 = zval[r0], zv1 = zval[r1];
        const float* m0 = M2I + (size_t)imax[r0] * 2048;
        const float* m1 = M2I + (size_t)imax[r1] * 2048;
        #pragma unroll
        for (int j = 0; j < 4; j++) {
            const int col = bcol + wn * 32 + j * 8 + ec;
            const float bz0 = biasI[col], bz1 = biasI[col + 1];
            const float v0 = acc[i][j][0] + bz0 + zv0 * m0[col];
            const float v1 = acc[i][j][1] + bz1 + zv0 * m0[col + 1];
            const float v2 = acc[i][j][2] + bz0 + zv1 * m1[col];
            const float v3 = acc[i][j][3] + bz1 + zv1 * m1[col + 1];
            const float p0 = __shfl_xor_sync(0xffffffffu, v0, 1);
            const float p1 = __shfl_xor_sync(0xffffffffu, v1, 1);
            const float p2 = __shfl_xor_sync(0xffffffffu, v2, 1);
            const float p3 = __shfl_xor_sync(0xffffffffu, v3, 1);
            const int h = col >> 2;
            int rw; float gi, gf, gg, go;
            if ((lane & 1) == 0) { rw = r0; gi = v0; gf = v1; gg = p0; go = p1; }
            else                 { rw = r1; gi = p2; gf = p3; gg = v2; go = v3; }
            const size_t idx = (size_t)rw * 512 + h;
            const float cnew = sigf(gf) * cx[idx] + sigf(gi) * tanhf(gg);
            cx[idx] = cnew;
            const float hv = sigf(go) * tanhf(cnew);
            if (NS == 2) split2h(hv, wo1, wo2, idx);
            else         wo1[idx] = __float2half_rn(hv);
        }
    }
}

// ---------------- softmax + straight-through (proven) ----------------
__global__ __launch_bounds__(256)
void softmax_st(const float* __restrict__ logits, const float* __restrict__ gumbel, int t,
                float* __restrict__ onehot, float* __restrict__ messages,
                int* __restrict__ imaxO, float* __restrict__ zvalO)
{
    const int b = blockIdx.x, tid = threadIdx.x;
    const float* pre = logits + (size_t)b * (L_ * D_) + (size_t)t * D_;
    const float* gm = gumbel + ((size_t)t * B_ + b) * D_;
    float y[4]; float vmax = -INFINITY; int imax = 0;
    #pragma unroll
    for (int q = 0; q < 4; q++) {
        const int d = tid + q * 256;
        y[q] = pre[d] + gm[d];
        if (y[q] > vmax) { vmax = y[q]; imax = d; }
    }
    __shared__ float sv[256]; __shared__ int si[256]; __shared__ float ss[256];
    sv[tid] = vmax; si[tid] = imax;
    __syncthreads();
    for (int s = 128; s > 0; s >>= 1) {
        if (tid < s) {
            const float ov = sv[tid + s]; const int oi = si[tid + s];
            if (ov > sv[tid] || (ov == sv[tid] && oi < si[tid])) { sv[tid] = ov; si[tid] = oi; }
        }
        __syncthreads();
    }
    vmax = sv[0]; imax = si[0];
    float ls = 0.f;
    #pragma unroll
    for (int q = 0; q < 4; q++) ls += expf(y[q] - vmax);
    ss[tid] = ls;
    __syncthreads();
    for (int s = 128; s > 0; s >>= 1) { if (tid < s) ss[tid] += ss[tid + s]; __syncthreads(); }
    const float sm = 1.f / ss[0];
    const float zval = sm + (1.f - sm);
    float* oh = onehot + (size_t)b * (L_ * D_) + (size_t)t * D_;
    #pragma unroll
    for (int q = 0; q < 4; q++) { const int d = tid + q * 256; oh[d] = (d == imax) ? zval : 0.f; }
    if (tid == 0) {
        messages[(size_t)b * L_ + t] = (float)imax;
        imaxO[b] = imax;
        zvalO[b] = zval;
    }
}

// ---------------- consolidated prep (proven) ----------------
__global__ void prep_all(const float* __restrict__ eWih, const float* __restrict__ eWhh,
                         const float* __restrict__ dWih, const float* __restrict__ dWhh,
                         const float* __restrict__ t2h_W, const float* __restrict__ h2t_W,
                         const float* __restrict__ in_W, const float* __restrict__ out_W,
                         const float* __restrict__ x,
                         __half* WhE1, __half* WhE2, __half* WiE1, __half* WiE2,
                         __half* WhD1, __half* WiD1, __half* WiD2,
                         __half* t2hT1, __half* t2hT2, __half* h2t1, __half* h2t2,
                         __half* inW1, __half* inW2, __half* outW1,
                         __half* x1, __half* x2,
                         __half* hxA, __half* hxB, __half* hx21,
                         float* cx2, float* bz, float* zv0, int* im0)
{
    int i = blockIdx.x * 256 + threadIdx.x;
    if (i < 1048576) {
        const int n = i >> 9, k = i & 511, r = ((n & 3) << 9) + (n >> 2);
        split2h(eWhh[(size_t)r * 512 + k], WhE1, WhE2, i);
        return;
    }
    i -= 1048576;
    if (i < 1048576) {
        const int n = i >> 9, k = i & 511, r = ((n & 3) << 9) + (n >> 2);
        split2h(eWih[(size_t)r * 512 + k], WiE1, WiE2, i);
        return;
    }
    i -= 1048576;
    if (i < 1048576) {
        const int n = i >> 9, k = i & 511, r = ((n & 3) << 9) + (n >> 2);
        WhD1[i] = __float2half_rn(dWhh[(size_t)r * 512 + k]);
        return;
    }
    i -= 1048576;
    if (i < 1048576) {
        const int n = i >> 9, k = i & 511, r = ((n & 3) << 9) + (n >> 2);
        split2h(dWih[(size_t)r * 512 + k], WiD1, WiD2, i);
        return;
    }
    i -= 1048576;
    if (i < 524288) {
        const int d = i >> 9, h = i & 511;
        split2h(t2h_W[(size_t)h * 1024 + d], t2hT1, t2hT2, i);
        return;
    }
    i -= 524288;
    if (i < 524288) { split2h(h2t_W[i], h2t1, h2t2, i); return; }
    i -= 524288;
    if (i < 262144) { split2h(in_W[i], inW1, inW2, i); return; }
    i -= 262144;
    if (i < 262144) { outW1[i] = __float2half_rn(out_W[i]); return; }
    i -= 262144;
    if (i < 1048576) { split2h(x[i], x1, x2, i); return; }
    i -= 1048576;
    if (i < 1048576) {
        const __half z = __float2half_rn(0.f);
        hxA[i] = z; hxB[i] = z; hx21[i] = z; cx2[i] = 0.f;
        if (i < 2048) { bz[i] = 0.f; }
        if (i < B_) { zv0[i] = 0.f; im0[i] = 0; }
    }
}

__global__ void bias_fold2(const float* __restrict__ eWih, const float* __restrict__ ebih,
                           const float* __restrict__ ebhh,
                           const float* __restrict__ dWih, const float* __restrict__ dbih,
                           const float* __restrict__ dbhh,
                           const float* __restrict__ t2hb,
                           float* __restrict__ b0e, float* __restrict__ b2e,
                           float* __restrict__ b2d)
{
    const int tid = blockIdx.x * 256 + threadIdx.x;
    if (tid < 2048) {
        const int n = tid, r = ((n & 3) << 9) + (n >> 2);
        const float s = ebih[r] + ebhh[r];
        float acc = 0.f;
        const float* wr = eWih + (size_t)r * 512;
        for (int k = 0; k < 512; k++) acc += t2hb[k] * wr[k];
        b0e[n] = s; b2e[n] = s + acc;
    } else if (tid < 4096) {
        const int n = tid - 2048, r = ((n & 3) << 9) + (n >> 2);
        const float s = dbih[r] + dbhh[r];
        float acc = 0.f;
        const float* wr = dWih + (size_t)r * 512;
        for (int k = 0; k < 512; k++) acc += t2hb[k] * wr[k];
        b2d[n] = s + acc;
    }
}

// ---------------- host ----------------
#define SYM(p, s) cudaGetSymbolAddress((void**)&p, s)

extern "C" void kernel_launch(void* const* d_in, const int* in_sizes, int n_in,
                              void* d_out, int out_size)
{
    const float* x = (const float*)d_in[0];
    const float* gumbel = (const float*)d_in[1];
    const float* in_W = (const float*)d_in[2];
    const float* in_b = (const float*)d_in[3];
    const float* out_W = (const float*)d_in[4];
    const float* out_b = (const float*)d_in[5];
    const float* eWih = (const float*)d_in[6];
    const float* eWhh = (const float*)d_in[7];
    const float* ebih = (const float*)d_in[8];
    const float* ebhh = (const float*)d_in[9];
    const float* dWih = (const float*)d_in[10];
    const float* dWhh = (const float*)d_in[11];
    const float* dbih = (const float*)d_in[12];
    const float* dbhh = (const float*)d_in[13];
    const float* h2t_W = (const float*)d_in[14];
    const float* h2t_b = (const float*)d_in[15];
    const float* t2h_W = (const float*)d_in[16];
    const float* t2h_b = (const float*)d_in[17];

    float* out = (float*)d_out;
    float* o_recon = out;
    float* o_oh = out + (size_t)B_ * O_;
    float* o_lg = o_oh + (size_t)B_ * L_ * D_;
    float* o_msg = o_lg + (size_t)B_ * L_ * D_;

    float *cx, *cx2, *M2e, *M2d, *b0e, *b2e, *b2d, *bz, *zvalL;
    int* imaxL;
    __half *WhE1, *WhE2, *WiE1, *WiE2, *WhD1, *WiD1, *WiD2;
    __half *t2hT1, *t2hT2, *h2t1, *h2t2, *inW1, *inW2, *outW1;
    __half *x1, *x2, *hxA, *hxB, *hxC, *hxD, *hx21, *hx21b;
    SYM(cx, g_cx); SYM(cx2, g_cx2);
    SYM(M2e, g_M2e); SYM(M2d, g_M2d);
    SYM(b0e, g_b0e); SYM(b2e, g_b2e); SYM(b2d, g_b2d); SYM(bz, g_bz);
    SYM(zvalL, g_zvalL); SYM(imaxL, g_imaxL);
    SYM(WhE1, g_WhE1); SYM(WhE2, g_WhE2); SYM(WiE1, g_WiE1); SYM(WiE2, g_WiE2);
    SYM(WhD1, g_WhD1); SYM(WiD1, g_WiD1); SYM(WiD2, g_WiD2);
    SYM(t2hT1, g_t2hT1); SYM(t2hT2, g_t2hT2); SYM(h2t1, g_h2t1); SYM(h2t2, g_h2t2);
    SYM(inW1, g_inW1); SYM(inW2, g_inW2); SYM(outW1, g_outW1);
    SYM(x1, g_x1); SYM(x2, g_x2);
    SYM(hxA, g_hxA); SYM(hxB, g_hxB); SYM(hxC, g_hxC); SYM(hxD, g_hxD);
    SYM(hx21, g_hx21); SYM(hx21b, g_hx21b);

    const int G2 = 3 * 2 * 2 * (int)TBK;   // 98304
    const int G1 = 3 * 1 * 2 * (int)TBK;   // 49152
    cudaFuncSetAttribute(gemm128<2>, cudaFuncAttributeMaxDynamicSharedMemorySize, G2);
    cudaFuncSetAttribute(gemm128<1>, cudaFuncAttributeMaxDynamicSharedMemorySize, G1);
    cudaFuncSetAttribute(gate128<2>, cudaFuncAttributeMaxDynamicSharedMemorySize, G2);
    cudaFuncSetAttribute(gate128<1>, cudaFuncAttributeMaxDynamicSharedMemorySize, G1);

    prep_all<<<30720, 256>>>(eWih, eWhh, dWih, dWhh, t2h_W, h2t_W, in_W, out_W, x,
                             WhE1, WhE2, WiE1, WiE2, WhD1, WiD1, WiD2,
                             t2hT1, t2hT2, h2t1, h2t2, inW1, inW2, outW1,
                             x1, x2, hxA, hxB, hx21, cx2, bz, zvalL, imaxL);
    bias_fold2<<<16, 256>>>(eWih, ebih, ebhh, dWih, dbih, dbhh, t2h_b, b0e, b2e, b2d);
    gemm128<2><<<dim3(16, 8), 256, G2>>>(t2hT1, t2hT2, WiE1, WiE2, bz, M2e, 512, 2048, 16);
    gemm128<2><<<dim3(16, 8), 256, G2>>>(t2hT1, t2hT2, WiD1, WiD2, bz, M2d, 512, 2048, 16);
    gemm128<2><<<dim3(4, 16), 256, G2>>>(x1, x2, inW1, inW2, in_b, cx, 512, 512, 16);

    // ---- encoder (launch 5 = first fused gate GEMM -> ncu target) ----
    for (int t = 0; t < L_; t++) {
        __half *hr1 = (t & 1) ? hxC : hxA, *hr2 = (t & 1) ? hxD : hxB;
        __half *hw1 = (t & 1) ? hxA : hxC, *hw2 = (t & 1) ? hxB : hxD;
        gate128<2><<<dim3(16, 16), 256, G2>>>(hr1, hr2, WhE1, WhE2,
            (t == 0) ? b0e : b2e, M2e, imaxL + (size_t)t * B_, zvalL + (size_t)t * B_,
            cx, hw1, hw2);
        gemm128<2><<<dim3(8, 16), 256, G2>>>(hw1, hw2, h2t1, h2t2, h2t_b,
            o_lg + (size_t)t * D_, 512, L_ * D_, 16);
        softmax_st<<<B_, 256>>>(o_lg, gumbel, t, o_oh, o_msg,
            imaxL + (size_t)(t + 1) * B_, zvalL + (size_t)(t + 1) * B_);
    }

    // ---- decoder ----
    for (int t = 0; t < L_; t++) {
        __half* hr = (t & 1) ? hx21b : hx21;
        __half* hw = (t & 1) ? hx21 : hx21b;
        gate128<1><<<dim3(16, 16), 256, G1>>>(hr, hr, WhD1, WhD1, b2d, M2d,
            imaxL + (size_t)(t + 1) * B_, zvalL + (size_t)(t + 1) * B_,
            cx2, hw, nullptr);
    }
    gemm128<1><<<dim3(4, 16), 256, G1>>>(hx21, hx21, outW1, outW1, out_b, o_recon,
                                         512, 512, 16);
}